// round 2
// baseline (speedup 1.0000x reference)
#include <cuda_runtime.h>
#include <math.h>

// Problem constants
#define NTOK  16384
#define DIN   2048
#define HMID  4096
#define NEXP  64
#define NSHARED 8
#define TOPK  2

// GEMM1 tiling
#define BM 128
#define BN 128
#define BK 16

// Router tiling
#define TM  16
#define BK2 128

// Output layout (flattened concat of the reference tuple)
#define G_OFF  0
#define LW_OFF (NTOK * NSHARED)                 // 131072
#define LI_OFF (LW_OFF + NTOK * TOPK)           // 163840
#define W_OFF  (LI_OFF + NTOK * TOPK)           // 196608

// Scratch: h = gelu(x @ W1 + b1), [NTOK, HMID] fp32 (268 MB, static device array)
__device__ float g_h[(size_t)NTOK * HMID];

typedef unsigned long long ull;

__device__ __forceinline__ void ffma2(ull &d, ull a, ull b) {
    asm("fma.rn.f32x2 %0, %1, %2, %0;" : "+l"(d) : "l"(a), "l"(b));
}
__device__ __forceinline__ ull pack2(float x, float y) {
    ull r; asm("mov.b64 %0, {%1, %2};" : "=l"(r) : "f"(x), "f"(y)); return r;
}
__device__ __forceinline__ float2 unpack2(ull v) {
    float2 f; asm("mov.b64 {%0, %1}, %2;" : "=f"(f.x), "=f"(f.y) : "l"(v)); return f;
}
__device__ __forceinline__ float gelu_exact(float v) {
    return 0.5f * v * (1.0f + erff(v * 0.70710678118654752440f));
}

// ---------------------------------------------------------------------------
// Kernel 1: h = gelu(x @ W1 + b1)
// x: [NTOK, DIN], W1: [DIN, HMID], b1: [HMID]
// 128x128 tile, BK=16, 256 threads, 8x8 per thread, packed f32x2 FMA.
// ---------------------------------------------------------------------------
__global__ void __launch_bounds__(256)
gemm1_gelu_kernel(const float* __restrict__ x,
                  const float* __restrict__ W1,
                  const float* __restrict__ b1) {
    __shared__ float As[2][BK][BM + 4];   // transposed A tile (padded)
    __shared__ float Bs[2][BK][BN];

    const int tid = threadIdx.x;
    const int row0 = blockIdx.y * BM;
    const int col0 = blockIdx.x * BN;

    // A-tile load mapping: 128 rows x 16 k  (2 x float4 per thread)
    const int ar  = tid >> 2;         // 0..63 (+64 second half)
    const int ac4 = (tid & 3) * 4;    // 0,4,8,12
    // B-tile load mapping: 16 k x 128 cols (2 x float4 per thread)
    const int bkr = tid >> 5;         // 0..7 (+8 second half)
    const int bc4 = (tid & 31) * 4;   // 0..124

    // compute mapping
    const int tx = tid & 15;          // col group
    const int ty = tid >> 4;          // row group
    const int rr0 = ty * 8;
    const int cc0 = tx * 8;

    ull acc[8][4];
#pragma unroll
    for (int i = 0; i < 8; i++)
#pragma unroll
        for (int j = 0; j < 4; j++) acc[i][j] = 0ULL;

    // prologue: load tile 0
    {
#pragma unroll
        for (int h = 0; h < 2; h++) {
            int r = ar + h * 64;
            float4 v = *reinterpret_cast<const float4*>(
                &x[(size_t)(row0 + r) * DIN + ac4]);
            As[0][ac4 + 0][r] = v.x; As[0][ac4 + 1][r] = v.y;
            As[0][ac4 + 2][r] = v.z; As[0][ac4 + 3][r] = v.w;
        }
#pragma unroll
        for (int h = 0; h < 2; h++) {
            int kk = bkr + h * 8;
            float4 v = *reinterpret_cast<const float4*>(
                &W1[(size_t)kk * HMID + col0 + bc4]);
            *reinterpret_cast<float4*>(&Bs[0][kk][bc4]) = v;
        }
    }
    __syncthreads();

    const int KT = DIN / BK;  // 128
    for (int kt = 0; kt < KT; kt++) {
        int buf = kt & 1;
        // prefetch next tile into the other buffer
        if (kt + 1 < KT) {
            int k0 = (kt + 1) * BK;
            int nb = buf ^ 1;
#pragma unroll
            for (int h = 0; h < 2; h++) {
                int r = ar + h * 64;
                float4 v = *reinterpret_cast<const float4*>(
                    &x[(size_t)(row0 + r) * DIN + k0 + ac4]);
                As[nb][ac4 + 0][r] = v.x; As[nb][ac4 + 1][r] = v.y;
                As[nb][ac4 + 2][r] = v.z; As[nb][ac4 + 3][r] = v.w;
            }
#pragma unroll
            for (int h = 0; h < 2; h++) {
                int kk = bkr + h * 8;
                float4 v = *reinterpret_cast<const float4*>(
                    &W1[(size_t)(k0 + kk) * HMID + col0 + bc4]);
                *reinterpret_cast<float4*>(&Bs[nb][kk][bc4]) = v;
            }
        }
#pragma unroll
        for (int kk = 0; kk < BK; kk++) {
            float4 a0 = *reinterpret_cast<const float4*>(&As[buf][kk][rr0]);
            float4 a1 = *reinterpret_cast<const float4*>(&As[buf][kk][rr0 + 4]);
            const double* bp = reinterpret_cast<const double*>(&Bs[buf][kk][cc0]);
            ull bb[4];
#pragma unroll
            for (int j = 0; j < 4; j++) {
                double bd = bp[j];
                bb[j] = *reinterpret_cast<ull*>(&bd);
            }
            float av[8] = {a0.x, a0.y, a0.z, a0.w, a1.x, a1.y, a1.z, a1.w};
#pragma unroll
            for (int i = 0; i < 8; i++) {
                ull aa = pack2(av[i], av[i]);
#pragma unroll
                for (int j = 0; j < 4; j++) ffma2(acc[i][j], aa, bb[j]);
            }
        }
        __syncthreads();
    }

    // epilogue: bias + gelu + store
    float bias[8];
#pragma unroll
    for (int j = 0; j < 8; j++) bias[j] = b1[col0 + cc0 + j];

#pragma unroll
    for (int i = 0; i < 8; i++) {
        float outv[8];
#pragma unroll
        for (int j = 0; j < 4; j++) {
            float2 c = unpack2(acc[i][j]);
            outv[2 * j + 0] = gelu_exact(c.x + bias[2 * j + 0]);
            outv[2 * j + 1] = gelu_exact(c.y + bias[2 * j + 1]);
        }
        size_t base = (size_t)(row0 + rr0 + i) * HMID + col0 + cc0;
        *reinterpret_cast<float4*>(&g_h[base])     = make_float4(outv[0], outv[1], outv[2], outv[3]);
        *reinterpret_cast<float4*>(&g_h[base + 4]) = make_float4(outv[4], outv[5], outv[6], outv[7]);
    }
}

// ---------------------------------------------------------------------------
// Kernel 2: logits = h @ W2 + b2, softmax, split shared/local, top-2,
//           write all four outputs.
// One block handles TM=16 tokens; 256 threads.
// thread -> (t = tid>>4, eg = tid&15) owns experts 4*eg..4*eg+3 of token t.
// ---------------------------------------------------------------------------
__global__ void __launch_bounds__(256)
router_kernel(const float* __restrict__ W2,
              const float* __restrict__ b2,
              float* __restrict__ out) {
    __shared__ float hs[TM][BK2];        // 8 KB
    __shared__ float w2s[BK2][NEXP];     // 32 KB
    __shared__ float lg[TM][NEXP];       // 4 KB
    __shared__ float sinv[TM];

    const int tid = threadIdx.x;
    const int tok0 = blockIdx.x * TM;
    const int t  = tid >> 4;
    const int eg = tid & 15;

    float tot0 = 0.f, tot1 = 0.f, tot2 = 0.f, tot3 = 0.f;

    for (int k0 = 0; k0 < HMID; k0 += BK2) {
        // load h tile: 16 x 128 floats = 512 float4, 2 per thread
#pragma unroll
        for (int h = 0; h < 2; h++) {
            int f = tid + 256 * h;
            int tr = f >> 5;
            int kc = (f & 31) << 2;
            float4 v = *reinterpret_cast<const float4*>(
                &g_h[(size_t)(tok0 + tr) * HMID + k0 + kc]);
            *reinterpret_cast<float4*>(&hs[tr][kc]) = v;
        }
        // load W2 tile: 128 x 64 floats = 2048 float4, 8 per thread
#pragma unroll
        for (int h = 0; h < 8; h++) {
            int f = tid + 256 * h;
            int kk = f >> 4;
            int e4 = (f & 15) << 2;
            float4 v = *reinterpret_cast<const float4*>(
                &W2[(size_t)(k0 + kk) * NEXP + e4]);
            *reinterpret_cast<float4*>(&w2s[kk][e4]) = v;
        }
        __syncthreads();

        float c0 = 0.f, c1 = 0.f, c2 = 0.f, c3 = 0.f;  // chunk partials
#pragma unroll 4
        for (int kk = 0; kk < BK2; kk++) {
            float a = hs[t][kk];
            float4 w = *reinterpret_cast<const float4*>(&w2s[kk][eg * 4]);
            c0 = fmaf(a, w.x, c0);
            c1 = fmaf(a, w.y, c1);
            c2 = fmaf(a, w.z, c2);
            c3 = fmaf(a, w.w, c3);
        }
        tot0 += c0; tot1 += c1; tot2 += c2; tot3 += c3;
        __syncthreads();
    }

    // logits -> smem (+ bias)
    lg[t][eg * 4 + 0] = tot0 + b2[eg * 4 + 0];
    lg[t][eg * 4 + 1] = tot1 + b2[eg * 4 + 1];
    lg[t][eg * 4 + 2] = tot2 + b2[eg * 4 + 2];
    lg[t][eg * 4 + 3] = tot3 + b2[eg * 4 + 3];
    __syncthreads();

    // per-token softmax + top-2 (threads 0..15, one token each)
    if (tid < TM) {
        const int tok = tok0 + tid;
        float mx = -1e30f;
#pragma unroll
        for (int e = 0; e < NEXP; e++) mx = fmaxf(mx, lg[tid][e]);
        float s = 0.f;
#pragma unroll
        for (int e = 0; e < NEXP; e++) {
            float ev = expf(lg[tid][e] - mx);
            lg[tid][e] = ev;     // store unnormalized exp back
            s += ev;
        }
        float inv = 1.0f / s;
        sinv[tid] = inv;

        // top-2 over local experts (8..63); strict > => lowest index on ties
        float v1 = -1.0f, v2 = -1.0f;
        int i1 = 0, i2 = 0;
#pragma unroll
        for (int e = NSHARED; e < NEXP; e++) {
            float v = lg[tid][e];
            if (v > v1)      { v2 = v1; i2 = i1; v1 = v; i1 = e; }
            else if (v > v2) { v2 = v;  i2 = e; }
        }
        // shared (global) expert weights
#pragma unroll
        for (int e = 0; e < NSHARED; e++)
            out[G_OFF + (size_t)tok * NSHARED + e] = lg[tid][e] * inv;
        // local top-2 weights + indices (relative to local block)
        out[LW_OFF + (size_t)tok * TOPK + 0] = v1 * inv;
        out[LW_OFF + (size_t)tok * TOPK + 1] = v2 * inv;
        out[LI_OFF + (size_t)tok * TOPK + 0] = (float)(i1 - NSHARED);
        out[LI_OFF + (size_t)tok * TOPK + 1] = (float)(i2 - NSHARED);
    }
    __syncthreads();

    // all threads write full weights matrix (coalesced)
    {
        float inv = sinv[t];
        float4 v = *reinterpret_cast<const float4*>(&lg[t][eg * 4]);
        v.x *= inv; v.y *= inv; v.z *= inv; v.w *= inv;
        *reinterpret_cast<float4*>(
            &out[W_OFF + (size_t)(tok0 + t) * NEXP + eg * 4]) = v;
    }
}

// ---------------------------------------------------------------------------
extern "C" void kernel_launch(void* const* d_in, const int* in_sizes, int n_in,
                              void* d_out, int out_size) {
    const float* x  = (const float*)d_in[0];
    const float* W1 = (const float*)d_in[1];
    const float* b1 = (const float*)d_in[2];
    const float* W2 = (const float*)d_in[3];
    const float* b2 = (const float*)d_in[4];
    float* out = (float*)d_out;

    dim3 g1(HMID / BN, NTOK / BM);   // (32, 128)
    gemm1_gelu_kernel<<<g1, 256>>>(x, W1, b1);

    router_kernel<<<NTOK / TM, 256>>>(W2, b2, out);
}

// round 4
// speedup vs baseline: 1.8198x; 1.8198x over previous
#include <cuda_runtime.h>
#include <cuda_fp16.h>
#include <math.h>
#include <stdint.h>

// ---------------------------------------------------------------------------
// Problem constants
// ---------------------------------------------------------------------------
#define NTOK  16384
#define DIN   2048
#define HMID  4096
#define NEXP  64
#define NSHARED 8
#define TOPK  2

// Output layout (flattened concat of the reference tuple)
#define G_OFF  0
#define LW_OFF (NTOK * NSHARED)
#define LI_OFF (LW_OFF + NTOK * TOPK)
#define W_OFF  (LI_OFF + NTOK * TOPK)

// ---------------------------------------------------------------------------
// Scratch (static device arrays; no allocation)
// ---------------------------------------------------------------------------
__device__ float  g_h[(size_t)NTOK * HMID];           // 268 MB
__device__ __half g_x0[(size_t)NTOK * DIN];           // 67 MB
__device__ __half g_x1[(size_t)NTOK * DIN];
__device__ __half g_w0[(size_t)HMID * DIN];           // 16.8 MB (W1^T)
__device__ __half g_w1[(size_t)HMID * DIN];

__device__ __forceinline__ uint32_t smem_u32(const void* p) {
    uint32_t a;
    asm("{ .reg .u64 t; cvta.to.shared.u64 t, %1; cvt.u32.u64 %0, t; }"
        : "=r"(a) : "l"(p));
    return a;
}

__device__ __forceinline__ float gelu_exact(float v) {
    return 0.5f * v * (1.0f + erff(v * 0.70710678118654752440f));
}

__device__ __forceinline__ void ldsm_x4(uint32_t* r, uint32_t addr) {
    asm volatile("ldmatrix.sync.aligned.m8n8.x4.shared.b16 {%0,%1,%2,%3}, [%4];"
                 : "=r"(r[0]), "=r"(r[1]), "=r"(r[2]), "=r"(r[3]) : "r"(addr));
}

__device__ __forceinline__ void mma16816(float* d, const uint32_t* a,
                                         uint32_t b0, uint32_t b1) {
    asm volatile(
        "mma.sync.aligned.m16n8k16.row.col.f32.f16.f16.f32 "
        "{%0,%1,%2,%3}, {%4,%5,%6,%7}, {%8,%9}, {%0,%1,%2,%3};"
        : "+f"(d[0]), "+f"(d[1]), "+f"(d[2]), "+f"(d[3])
        : "r"(a[0]), "r"(a[1]), "r"(a[2]), "r"(a[3]), "r"(b0), "r"(b1));
}

#define CP_ASYNC16(dst, src) \
    asm volatile("cp.async.cg.shared.global [%0], [%1], 16;" \
                 :: "r"(dst), "l"(src) : "memory")
#define CP_COMMIT() asm volatile("cp.async.commit_group;" ::: "memory")

// ---------------------------------------------------------------------------
// conv_x: split x into 2 fp16 limb planes (row-major, K contiguous)
// ---------------------------------------------------------------------------
__global__ void __launch_bounds__(256)
conv_x_kernel(const float* __restrict__ x) {
    size_t i = ((size_t)blockIdx.x * 256 + threadIdx.x) * 4;
    float4 v = *reinterpret_cast<const float4*>(&x[i]);
    float a[4] = {v.x, v.y, v.z, v.w};
    unsigned short u0[4], u1[4];
#pragma unroll
    for (int j = 0; j < 4; j++) {
        __half h0 = __float2half_rn(a[j]);
        float r = a[j] - __half2float(h0);
        __half h1 = __float2half_rn(r);
        u0[j] = __half_as_ushort(h0);
        u1[j] = __half_as_ushort(h1);
    }
    *reinterpret_cast<uint2*>(&g_x0[i]) =
        make_uint2((uint32_t)u0[0] | ((uint32_t)u0[1] << 16),
                   (uint32_t)u0[2] | ((uint32_t)u0[3] << 16));
    *reinterpret_cast<uint2*>(&g_x1[i]) =
        make_uint2((uint32_t)u1[0] | ((uint32_t)u1[1] << 16),
                   (uint32_t)u1[2] | ((uint32_t)u1[3] << 16));
}

// ---------------------------------------------------------------------------
// conv_w1: transpose W1 [K,N] -> [N,K], split into 2 fp16 limb planes
// ---------------------------------------------------------------------------
__global__ void __launch_bounds__(256)
conv_w1_kernel(const float* __restrict__ W1) {
    __shared__ float tile[32][33];
    const int tx = threadIdx.x;      // 0..31
    const int ty = threadIdx.y;      // 0..7
    const int n0 = blockIdx.x * 32;
    const int k0 = blockIdx.y * 32;
#pragma unroll
    for (int j = 0; j < 4; j++)
        tile[ty + j * 8][tx] = W1[(size_t)(k0 + ty + j * 8) * HMID + n0 + tx];
    __syncthreads();
#pragma unroll
    for (int j = 0; j < 4; j++) {
        float v = tile[tx][ty + j * 8];
        __half h0 = __float2half_rn(v);
        float r = v - __half2float(h0);
        __half h1 = __float2half_rn(r);
        size_t o = (size_t)(n0 + ty + j * 8) * DIN + k0 + tx;
        g_w0[o] = h0;
        g_w1[o] = h1;
    }
}

// ---------------------------------------------------------------------------
// gemm1: h = gelu(x @ W1 + b1) via mma.sync fp16 2-limb, 3 products.
// CTA 128(M) x 128(N), K-chunk 32, 3-stage cp.async pipeline.
// SMEM stage: A0,A1,B0,B1 tiles [128 rows][40 halfs] (80B padded stride).
// ---------------------------------------------------------------------------
#define ROWB    80                     // bytes per smem row (32 halfs + pad)
#define TILEB   (128 * ROWB)           // 10240
#define STAGEB  (4 * TILEB)            // 40960
#define NSTAGE  3
#define SMEM_GEMM (NSTAGE * STAGEB)    // 122880
#define KT (DIN / 32)                  // 64

__global__ void __launch_bounds__(256)
gemm1_hmma_kernel(const float* __restrict__ b1) {
    extern __shared__ char smem[];
    const uint32_t sbase = smem_u32(smem);
    const int tid = threadIdx.x;
    const int wid = tid >> 5;
    const int lid = tid & 31;
    const int row0 = blockIdx.y * 128;   // M
    const int col0 = blockIdx.x * 128;   // N
    const int wm = (wid >> 2) * 64;      // warp M offset in tile
    const int wn = (wid & 3) * 32;       // warp N offset in tile

    // ---- loader mapping: thread -> (row = tid>>1, 2 x 16B chunks) ----
    const int lr  = tid >> 1;
    const int cc  = (tid & 1) * 2;       // chunk index base (of 4 per row)
    const char* gA0 = (const char*)(g_x0 + (size_t)(row0 + lr) * DIN) + cc * 16;
    const char* gA1 = (const char*)(g_x1 + (size_t)(row0 + lr) * DIN) + cc * 16;
    const char* gB0 = (const char*)(g_w0 + (size_t)(col0 + lr) * DIN) + cc * 16;
    const char* gB1 = (const char*)(g_w1 + (size_t)(col0 + lr) * DIN) + cc * 16;
    const uint32_t sOff = (uint32_t)lr * ROWB + cc * 16;

    float acc[4][4][4];
#pragma unroll
    for (int i = 0; i < 4; i++)
#pragma unroll
        for (int j = 0; j < 4; j++)
#pragma unroll
            for (int k = 0; k < 4; k++) acc[i][j][k] = 0.f;

    auto load_stage = [&](int s, int kt) {
        const uint32_t sb = sbase + s * STAGEB + sOff;
        const int go = kt * 64;          // 32 halfs = 64 bytes along K
        CP_ASYNC16(sb,                  gA0 + go);
        CP_ASYNC16(sb + 16,             gA0 + go + 16);
        CP_ASYNC16(sb + TILEB,          gA1 + go);
        CP_ASYNC16(sb + TILEB + 16,     gA1 + go + 16);
        CP_ASYNC16(sb + 2 * TILEB,      gB0 + go);
        CP_ASYNC16(sb + 2 * TILEB + 16, gB0 + go + 16);
        CP_ASYNC16(sb + 3 * TILEB,      gB1 + go);
        CP_ASYNC16(sb + 3 * TILEB + 16, gB1 + go + 16);
        CP_COMMIT();
    };

    // ldmatrix address components (constant per thread)
    const uint32_t aRow = (uint32_t)(wm + (lid & 15)) * ROWB + (lid >> 4) * 16;
    const uint32_t bRow = (uint32_t)(wn + (lid & 7) + ((lid >> 4) & 1) * 8) * ROWB
                        + ((lid >> 3) & 1) * 16;

#pragma unroll
    for (int s = 0; s < NSTAGE; s++) load_stage(s, s);

    for (int kt = 0; kt < KT; kt++) {
        if (kt < KT - 2) {
            asm volatile("cp.async.wait_group 2;" ::: "memory");
        } else {
            asm volatile("cp.async.wait_group 0;" ::: "memory");
        }
        __syncthreads();

        const uint32_t sb = sbase + (kt % NSTAGE) * STAGEB;
#pragma unroll
        for (int k16 = 0; k16 < 2; k16++) {
            const uint32_t kOff = k16 * 32;
            uint32_t a[2][4][4];
#pragma unroll
            for (int limb = 0; limb < 2; limb++) {
                const uint32_t ab = sb + limb * TILEB + aRow + kOff;
#pragma unroll
                for (int mt = 0; mt < 4; mt++)
                    ldsm_x4(a[limb][mt], ab + mt * 16 * ROWB);
            }
            uint32_t b[2][2][4];
#pragma unroll
            for (int limb = 0; limb < 2; limb++) {
                const uint32_t bb = sb + (2 + limb) * TILEB + bRow + kOff;
#pragma unroll
                for (int nt2 = 0; nt2 < 2; nt2++)
                    ldsm_x4(b[limb][nt2], bb + nt2 * 16 * ROWB);
            }
#pragma unroll
            for (int mt = 0; mt < 4; mt++) {
#pragma unroll
                for (int nt = 0; nt < 4; nt++) {
                    const int n2 = nt >> 1, h = (nt & 1) * 2;
                    mma16816(acc[mt][nt], a[0][mt], b[0][n2][h], b[0][n2][h + 1]);
                    mma16816(acc[mt][nt], a[0][mt], b[1][n2][h], b[1][n2][h + 1]);
                    mma16816(acc[mt][nt], a[1][mt], b[0][n2][h], b[0][n2][h + 1]);
                }
            }
        }
        __syncthreads();
        if (kt + NSTAGE < KT) load_stage(kt % NSTAGE, kt + NSTAGE);
    }

    // ---- epilogue: bias + gelu + store fp32 ----
    const int g = lid >> 2;
    const int i2 = (lid & 3) * 2;
#pragma unroll
    for (int nt = 0; nt < 4; nt++) {
        const int col = col0 + wn + nt * 8 + i2;
        const float bx = b1[col], by = b1[col + 1];
#pragma unroll
        for (int mt = 0; mt < 4; mt++) {
            const int row = row0 + wm + mt * 16 + g;
            float2 lo, hi;
            lo.x = gelu_exact(acc[mt][nt][0] + bx);
            lo.y = gelu_exact(acc[mt][nt][1] + by);
            hi.x = gelu_exact(acc[mt][nt][2] + bx);
            hi.y = gelu_exact(acc[mt][nt][3] + by);
            *reinterpret_cast<float2*>(&g_h[(size_t)row * HMID + col]) = lo;
            *reinterpret_cast<float2*>(&g_h[(size_t)(row + 8) * HMID + col]) = hi;
        }
    }
}

// ---------------------------------------------------------------------------
// router: logits = h @ W2 + b2, softmax, split shared/local, top-2, outputs.
// 32 tokens per block; thread (t = tid>>4, eg = tid&15) handles tokens t and
// t+16 for experts 4*eg..4*eg+3.
// ---------------------------------------------------------------------------
#define SMEM_ROUTER ((32 * 128 + 128 * 64 + 32 * 64 + 32) * 4)   // 57472

__global__ void __launch_bounds__(256)
router_kernel(const float* __restrict__ W2,
              const float* __restrict__ b2,
              float* __restrict__ out) {
    extern __shared__ float rs[];
    float* hs   = rs;                   // [32][128]
    float* w2s  = rs + 32 * 128;        // [128][64]
    float* lg   = w2s + 128 * 64;       // [32][64]
    float* sinv = lg + 32 * 64;         // [32]

    const int tid = threadIdx.x;
    const int tok0 = blockIdx.x * 32;
    const int t  = tid >> 4;            // 0..15
    const int eg = tid & 15;

    float A0[4] = {0.f, 0.f, 0.f, 0.f};
    float A1[4] = {0.f, 0.f, 0.f, 0.f};

    for (int k0 = 0; k0 < HMID; k0 += 128) {
#pragma unroll
        for (int hh = 0; hh < 4; hh++) {
            int f = tid + 256 * hh;
            int tr = f >> 5;
            int kc = (f & 31) << 2;
            *reinterpret_cast<float4*>(&hs[tr * 128 + kc]) =
                *reinterpret_cast<const float4*>(
                    &g_h[(size_t)(tok0 + tr) * HMID + k0 + kc]);
        }
#pragma unroll
        for (int hh = 0; hh < 8; hh++) {
            int f = tid + 256 * hh;
            int kk = f >> 4;
            int e4 = (f & 15) << 2;
            *reinterpret_cast<float4*>(&w2s[kk * 64 + e4]) =
                *reinterpret_cast<const float4*>(&W2[(size_t)(k0 + kk) * NEXP + e4]);
        }
        __syncthreads();

        float c0[4] = {0.f, 0.f, 0.f, 0.f};
        float c1[4] = {0.f, 0.f, 0.f, 0.f};
#pragma unroll 4
        for (int kk = 0; kk < 128; kk++) {
            float a0 = hs[t * 128 + kk];
            float a1 = hs[(t + 16) * 128 + kk];
            float4 w = *reinterpret_cast<const float4*>(&w2s[kk * 64 + eg * 4]);
            c0[0] = fmaf(a0, w.x, c0[0]);
            c0[1] = fmaf(a0, w.y, c0[1]);
            c0[2] = fmaf(a0, w.z, c0[2]);
            c0[3] = fmaf(a0, w.w, c0[3]);
            c1[0] = fmaf(a1, w.x, c1[0]);
            c1[1] = fmaf(a1, w.y, c1[1]);
            c1[2] = fmaf(a1, w.z, c1[2]);
            c1[3] = fmaf(a1, w.w, c1[3]);
        }
#pragma unroll
        for (int j = 0; j < 4; j++) { A0[j] += c0[j]; A1[j] += c1[j]; }
        __syncthreads();
    }

#pragma unroll
    for (int j = 0; j < 4; j++) {
        float bb = b2[eg * 4 + j];
        lg[t * 64 + eg * 4 + j] = A0[j] + bb;
        lg[(t + 16) * 64 + eg * 4 + j] = A1[j] + bb;
    }
    __syncthreads();

    if (tid < 32) {
        const int tok = tok0 + tid;
        float mx = -1e30f;
#pragma unroll
        for (int e = 0; e < NEXP; e++) mx = fmaxf(mx, lg[tid * 64 + e]);
        float s = 0.f;
#pragma unroll
        for (int e = 0; e < NEXP; e++) {
            float ev = expf(lg[tid * 64 + e] - mx);
            lg[tid * 64 + e] = ev;
            s += ev;
        }
        float inv = 1.0f / s;
        sinv[tid] = inv;

        float v1 = -1.0f, v2 = -1.0f;
        int i1 = 0, i2 = 0;
#pragma unroll
        for (int e = NSHARED; e < NEXP; e++) {
            float v = lg[tid * 64 + e];
            if (v > v1)      { v2 = v1; i2 = i1; v1 = v; i1 = e; }
            else if (v > v2) { v2 = v;  i2 = e; }
        }
#pragma unroll
        for (int e = 0; e < NSHARED; e++)
            out[G_OFF + (size_t)tok * NSHARED + e] = lg[tid * 64 + e] * inv;
        out[LW_OFF + (size_t)tok * TOPK + 0] = v1 * inv;
        out[LW_OFF + (size_t)tok * TOPK + 1] = v2 * inv;
        out[LI_OFF + (size_t)tok * TOPK + 0] = (float)(i1 - NSHARED);
        out[LI_OFF + (size_t)tok * TOPK + 1] = (float)(i2 - NSHARED);
    }
    __syncthreads();

#pragma unroll
    for (int hh = 0; hh < 2; hh++) {
        int f = tid + 256 * hh;
        int tr = f >> 4;
        int ec = f & 15;
        float inv = sinv[tr];
        float4 v = *reinterpret_cast<const float4*>(&lg[tr * 64 + ec * 4]);
        v.x *= inv; v.y *= inv; v.z *= inv; v.w *= inv;
        *reinterpret_cast<float4*>(
            &out[W_OFF + (size_t)(tok0 + tr) * NEXP + ec * 4]) = v;
    }
}

// ---------------------------------------------------------------------------
extern "C" void kernel_launch(void* const* d_in, const int* in_sizes, int n_in,
                              void* d_out, int out_size) {
    const float* x  = (const float*)d_in[0];
    const float* W1 = (const float*)d_in[1];
    const float* b1 = (const float*)d_in[2];
    const float* W2 = (const float*)d_in[3];
    const float* b2 = (const float*)d_in[4];
    float* out = (float*)d_out;

    static int attr_done = 0;
    if (!attr_done) {
        cudaFuncSetAttribute(gemm1_hmma_kernel,
                             cudaFuncAttributeMaxDynamicSharedMemorySize, SMEM_GEMM);
        cudaFuncSetAttribute(router_kernel,
                             cudaFuncAttributeMaxDynamicSharedMemorySize, SMEM_ROUTER);
        attr_done = 1;
    }

    conv_x_kernel<<<(NTOK * DIN) / (256 * 4), 256>>>(x);
    conv_w1_kernel<<<dim3(HMID / 32, DIN / 32), dim3(32, 8)>>>(W1);
    gemm1_hmma_kernel<<<dim3(HMID / 128, NTOK / 128), 256, SMEM_GEMM>>>(b1);
    router_kernel<<<NTOK / 32, 256, SMEM_ROUTER>>>(W2, b2, out);
}

// round 5
// speedup vs baseline: 2.4088x; 1.3237x over previous
#include <cuda_runtime.h>
#include <cuda_fp16.h>
#include <math.h>
#include <stdint.h>

// ---------------------------------------------------------------------------
// Problem constants
// ---------------------------------------------------------------------------
#define NTOK  16384
#define DIN   2048
#define HMID  4096
#define NEXP  64
#define NSHARED 8
#define TOPK  2

// Output layout (flattened concat of the reference tuple)
#define G_OFF  0
#define LW_OFF (NTOK * NSHARED)
#define LI_OFF (LW_OFF + NTOK * TOPK)
#define W_OFF  (LI_OFF + NTOK * TOPK)

// ---------------------------------------------------------------------------
// Scratch (static device arrays; no allocation)
// ---------------------------------------------------------------------------
__device__ __half g_x0[(size_t)NTOK * DIN];           // x limb planes
__device__ __half g_x1[(size_t)NTOK * DIN];
__device__ __half g_w0[(size_t)HMID * DIN];           // W1^T limb planes
__device__ __half g_w1[(size_t)HMID * DIN];
__device__ __half g_h0[(size_t)NTOK * HMID];          // h limb planes
__device__ __half g_h1[(size_t)NTOK * HMID];
__device__ __half g_u0[(size_t)NEXP * HMID];          // W2^T limb planes
__device__ __half g_u1[(size_t)NEXP * HMID];

__device__ __forceinline__ uint32_t smem_u32(const void* p) {
    uint32_t a;
    asm("{ .reg .u64 t; cvta.to.shared.u64 t, %1; cvt.u32.u64 %0, t; }"
        : "=r"(a) : "l"(p));
    return a;
}

__device__ __forceinline__ float gelu_exact(float v) {
    return 0.5f * v * (1.0f + erff(v * 0.70710678118654752440f));
}

__device__ __forceinline__ void ldsm_x4(uint32_t* r, uint32_t addr) {
    asm volatile("ldmatrix.sync.aligned.m8n8.x4.shared.b16 {%0,%1,%2,%3}, [%4];"
                 : "=r"(r[0]), "=r"(r[1]), "=r"(r[2]), "=r"(r[3]) : "r"(addr));
}

__device__ __forceinline__ void mma16816(float* d, const uint32_t* a,
                                         uint32_t b0, uint32_t b1) {
    asm volatile(
        "mma.sync.aligned.m16n8k16.row.col.f32.f16.f16.f32 "
        "{%0,%1,%2,%3}, {%4,%5,%6,%7}, {%8,%9}, {%0,%1,%2,%3};"
        : "+f"(d[0]), "+f"(d[1]), "+f"(d[2]), "+f"(d[3])
        : "r"(a[0]), "r"(a[1]), "r"(a[2]), "r"(a[3]), "r"(b0), "r"(b1));
}

#define CP_ASYNC16(dst, src) \
    asm volatile("cp.async.cg.shared.global [%0], [%1], 16;" \
                 :: "r"(dst), "l"(src) : "memory")
#define CP_COMMIT() asm volatile("cp.async.commit_group;" ::: "memory")

__device__ __forceinline__ uint32_t pack_limbs(float x, float y,
                                               float& rx, float& ry) {
    __half hx = __float2half_rn(x), hy = __float2half_rn(y);
    rx = x - __half2float(hx);
    ry = y - __half2float(hy);
    return (uint32_t)__half_as_ushort(hx) | ((uint32_t)__half_as_ushort(hy) << 16);
}

// ---------------------------------------------------------------------------
// conv_x: split x into 2 fp16 limb planes (row-major, K contiguous)
// ---------------------------------------------------------------------------
__global__ void __launch_bounds__(256)
conv_x_kernel(const float* __restrict__ x) {
    size_t i = ((size_t)blockIdx.x * 256 + threadIdx.x) * 4;
    float4 v = *reinterpret_cast<const float4*>(&x[i]);
    float a[4] = {v.x, v.y, v.z, v.w};
    unsigned short u0[4], u1[4];
#pragma unroll
    for (int j = 0; j < 4; j++) {
        __half h0 = __float2half_rn(a[j]);
        float r = a[j] - __half2float(h0);
        __half h1 = __float2half_rn(r);
        u0[j] = __half_as_ushort(h0);
        u1[j] = __half_as_ushort(h1);
    }
    *reinterpret_cast<uint2*>(&g_x0[i]) =
        make_uint2((uint32_t)u0[0] | ((uint32_t)u0[1] << 16),
                   (uint32_t)u0[2] | ((uint32_t)u0[3] << 16));
    *reinterpret_cast<uint2*>(&g_x1[i]) =
        make_uint2((uint32_t)u1[0] | ((uint32_t)u1[1] << 16),
                   (uint32_t)u1[2] | ((uint32_t)u1[3] << 16));
}

// ---------------------------------------------------------------------------
// conv_w1: transpose W1 [K,N] -> [N,K], split into 2 fp16 limb planes
// ---------------------------------------------------------------------------
__global__ void __launch_bounds__(256)
conv_w1_kernel(const float* __restrict__ W1) {
    __shared__ float tile[32][33];
    const int tx = threadIdx.x, ty = threadIdx.y;
    const int n0 = blockIdx.x * 32;
    const int k0 = blockIdx.y * 32;
#pragma unroll
    for (int j = 0; j < 4; j++)
        tile[ty + j * 8][tx] = W1[(size_t)(k0 + ty + j * 8) * HMID + n0 + tx];
    __syncthreads();
#pragma unroll
    for (int j = 0; j < 4; j++) {
        float v = tile[tx][ty + j * 8];
        __half h0 = __float2half_rn(v);
        float r = v - __half2float(h0);
        size_t o = (size_t)(n0 + ty + j * 8) * DIN + k0 + tx;
        g_w0[o] = h0;
        g_w1[o] = __float2half_rn(r);
    }
}

// ---------------------------------------------------------------------------
// conv_w2: transpose W2 [K=4096, 64] -> [64][4096], split into 2 limb planes
// ---------------------------------------------------------------------------
__global__ void __launch_bounds__(256)
conv_w2_kernel(const float* __restrict__ W2) {
    __shared__ float tile[32][33];
    const int tx = threadIdx.x, ty = threadIdx.y;
    const int n0 = blockIdx.x * 32;
    const int k0 = blockIdx.y * 32;
#pragma unroll
    for (int j = 0; j < 4; j++)
        tile[ty + j * 8][tx] = W2[(size_t)(k0 + ty + j * 8) * NEXP + n0 + tx];
    __syncthreads();
#pragma unroll
    for (int j = 0; j < 4; j++) {
        float v = tile[tx][ty + j * 8];
        __half h0 = __float2half_rn(v);
        float r = v - __half2float(h0);
        size_t o = (size_t)(n0 + ty + j * 8) * HMID + k0 + tx;
        g_u0[o] = h0;
        g_u1[o] = __float2half_rn(r);
    }
}

// ---------------------------------------------------------------------------
// gemm1: h = gelu(x @ W1 + b1) via mma.sync fp16 2-limb, 3 products.
// CTA 128x128, K-chunk 32, 2-stage cp.async pipeline, 2 CTAs/SM.
// Epilogue writes h as fp16 limb planes g_h0/g_h1.
// ---------------------------------------------------------------------------
#define ROWB    80
#define TILEB   (128 * ROWB)           // 10240
#define STAGEB  (4 * TILEB)            // 40960
#define NSTAGE  2
#define SMEM_GEMM (NSTAGE * STAGEB)    // 81920
#define KT (DIN / 32)                  // 64

__global__ void __launch_bounds__(256, 2)
gemm1_hmma_kernel(const float* __restrict__ b1) {
    extern __shared__ char smem[];
    const uint32_t sbase = smem_u32(smem);
    const int tid = threadIdx.x;
    const int wid = tid >> 5;
    const int lid = tid & 31;
    const int row0 = blockIdx.y * 128;
    const int col0 = blockIdx.x * 128;
    const int wm = (wid >> 2) * 64;
    const int wn = (wid & 3) * 32;

    const int lr  = tid >> 1;
    const int cc  = (tid & 1) * 2;
    const char* gA0 = (const char*)(g_x0 + (size_t)(row0 + lr) * DIN) + cc * 16;
    const char* gA1 = (const char*)(g_x1 + (size_t)(row0 + lr) * DIN) + cc * 16;
    const char* gB0 = (const char*)(g_w0 + (size_t)(col0 + lr) * DIN) + cc * 16;
    const char* gB1 = (const char*)(g_w1 + (size_t)(col0 + lr) * DIN) + cc * 16;
    const uint32_t sOff = (uint32_t)lr * ROWB + cc * 16;

    float acc[4][4][4];
#pragma unroll
    for (int i = 0; i < 4; i++)
#pragma unroll
        for (int j = 0; j < 4; j++)
#pragma unroll
            for (int k = 0; k < 4; k++) acc[i][j][k] = 0.f;

    auto load_stage = [&](int s, int kt) {
        const uint32_t sb = sbase + s * STAGEB + sOff;
        const int go = kt * 64;
        CP_ASYNC16(sb,                  gA0 + go);
        CP_ASYNC16(sb + 16,             gA0 + go + 16);
        CP_ASYNC16(sb + TILEB,          gA1 + go);
        CP_ASYNC16(sb + TILEB + 16,     gA1 + go + 16);
        CP_ASYNC16(sb + 2 * TILEB,      gB0 + go);
        CP_ASYNC16(sb + 2 * TILEB + 16, gB0 + go + 16);
        CP_ASYNC16(sb + 3 * TILEB,      gB1 + go);
        CP_ASYNC16(sb + 3 * TILEB + 16, gB1 + go + 16);
        CP_COMMIT();
    };

    const uint32_t aRow = (uint32_t)(wm + (lid & 15)) * ROWB + (lid >> 4) * 16;
    const uint32_t bRow = (uint32_t)(wn + (lid & 7) + ((lid >> 4) & 1) * 8) * ROWB
                        + ((lid >> 3) & 1) * 16;

    load_stage(0, 0);
    load_stage(1, 1);

    for (int kt = 0; kt < KT; kt++) {
        if (kt < KT - 1) {
            asm volatile("cp.async.wait_group 1;" ::: "memory");
        } else {
            asm volatile("cp.async.wait_group 0;" ::: "memory");
        }
        __syncthreads();

        const uint32_t sb = sbase + (kt & 1) * STAGEB;
#pragma unroll
        for (int k16 = 0; k16 < 2; k16++) {
            const uint32_t kOff = k16 * 32;
            uint32_t b0[2][4], b1f[2][4];
#pragma unroll
            for (int nt2 = 0; nt2 < 2; nt2++) {
                ldsm_x4(b0[nt2],  sb + 2 * TILEB + bRow + kOff + nt2 * 16 * ROWB);
                ldsm_x4(b1f[nt2], sb + 3 * TILEB + bRow + kOff + nt2 * 16 * ROWB);
            }
            uint32_t a0[4][4];
#pragma unroll
            for (int mt = 0; mt < 4; mt++)
                ldsm_x4(a0[mt], sb + aRow + kOff + mt * 16 * ROWB);
#pragma unroll
            for (int mt = 0; mt < 4; mt++) {
#pragma unroll
                for (int nt = 0; nt < 4; nt++) {
                    const int n2 = nt >> 1, h = (nt & 1) * 2;
                    mma16816(acc[mt][nt], a0[mt], b0[n2][h],  b0[n2][h + 1]);
                    mma16816(acc[mt][nt], a0[mt], b1f[n2][h], b1f[n2][h + 1]);
                }
            }
            uint32_t a1[4][4];
#pragma unroll
            for (int mt = 0; mt < 4; mt++)
                ldsm_x4(a1[mt], sb + TILEB + aRow + kOff + mt * 16 * ROWB);
#pragma unroll
            for (int mt = 0; mt < 4; mt++) {
#pragma unroll
                for (int nt = 0; nt < 4; nt++) {
                    const int n2 = nt >> 1, h = (nt & 1) * 2;
                    mma16816(acc[mt][nt], a1[mt], b0[n2][h], b0[n2][h + 1]);
                }
            }
        }
        __syncthreads();
        if (kt + 2 < KT) load_stage(kt & 1, kt + 2);
    }

    // epilogue: bias + gelu + split into fp16 limbs + store
    const int g = lid >> 2;
    const int i2 = (lid & 3) * 2;
#pragma unroll
    for (int nt = 0; nt < 4; nt++) {
        const int col = col0 + wn + nt * 8 + i2;
        const float bx = b1[col], by = b1[col + 1];
#pragma unroll
        for (int mt = 0; mt < 4; mt++) {
            const int row = row0 + wm + mt * 16 + g;
            float lox = gelu_exact(acc[mt][nt][0] + bx);
            float loy = gelu_exact(acc[mt][nt][1] + by);
            float hix = gelu_exact(acc[mt][nt][2] + bx);
            float hiy = gelu_exact(acc[mt][nt][3] + by);
            float r0, r1, r2, r3;
            uint32_t p0 = pack_limbs(lox, loy, r0, r1);
            uint32_t p1 = pack_limbs(hix, hiy, r2, r3);
            size_t o0 = (size_t)row * HMID + col;
            size_t o1 = (size_t)(row + 8) * HMID + col;
            *reinterpret_cast<uint32_t*>(&g_h0[o0]) = p0;
            *reinterpret_cast<uint32_t*>(&g_h0[o1]) = p1;
            __half q0 = __float2half_rn(r0), q1 = __float2half_rn(r1);
            __half q2 = __float2half_rn(r2), q3 = __float2half_rn(r3);
            *reinterpret_cast<uint32_t*>(&g_h1[o0]) =
                (uint32_t)__half_as_ushort(q0) | ((uint32_t)__half_as_ushort(q1) << 16);
            *reinterpret_cast<uint32_t*>(&g_h1[o1]) =
                (uint32_t)__half_as_ushort(q2) | ((uint32_t)__half_as_ushort(q3) << 16);
        }
    }
}

// ---------------------------------------------------------------------------
// router: logits = h @ W2 + b2 via HMMA (2-limb, 3 products), then softmax,
// shared/local split, top-2, all outputs. CTA = 128 tokens x 64 experts.
// ---------------------------------------------------------------------------
#define R_ATILE (128 * ROWB)                 // 10240 per limb
#define R_BTILE (64 * ROWB)                  // 5120 per limb
#define R_STAGE (2 * R_ATILE + 2 * R_BTILE)  // 30720
#define R_NSTAGE 3
#define R_KT (HMID / 32)                     // 128
#define LGS 66
#define SMEM_ROUTER (R_NSTAGE * R_STAGE + 128 * LGS * 4 + 512)   // 126464

__global__ void __launch_bounds__(256)
router_hmma_kernel(const float* __restrict__ b2, float* __restrict__ out) {
    extern __shared__ char smem[];
    const uint32_t sbase = smem_u32(smem);
    float* lg   = reinterpret_cast<float*>(smem + R_NSTAGE * R_STAGE);
    float* sinv = lg + 128 * LGS;

    const int tid = threadIdx.x;
    const int wid = tid >> 5;
    const int lid = tid & 31;
    const int tok0 = blockIdx.x * 128;
    const int wm = (wid >> 1) * 32;
    const int wn = (wid & 1) * 32;

    // loaders: A (h limbs): lr = tid>>1, 2 chunks; B (W2^T limbs): row tid>>2, chunk tid&3
    const int lr  = tid >> 1;
    const int cc  = (tid & 1) * 2;
    const char* gA0 = (const char*)(g_h0 + (size_t)(tok0 + lr) * HMID) + cc * 16;
    const char* gA1 = (const char*)(g_h1 + (size_t)(tok0 + lr) * HMID) + cc * 16;
    const uint32_t sA = (uint32_t)lr * ROWB + cc * 16;
    const int br = tid >> 2;
    const int bc = tid & 3;
    const char* gB0 = (const char*)(g_u0 + (size_t)br * HMID) + bc * 16;
    const char* gB1 = (const char*)(g_u1 + (size_t)br * HMID) + bc * 16;
    const uint32_t sB = (uint32_t)br * ROWB + bc * 16;

    float acc[2][4][4];
#pragma unroll
    for (int i = 0; i < 2; i++)
#pragma unroll
        for (int j = 0; j < 4; j++)
#pragma unroll
            for (int k = 0; k < 4; k++) acc[i][j][k] = 0.f;

    auto load_stage = [&](int s, int kt) {
        const uint32_t sb = sbase + s * R_STAGE;
        const int go = kt * 64;
        CP_ASYNC16(sb + sA,      gA0 + go);
        CP_ASYNC16(sb + sA + 16, gA0 + go + 16);
        CP_ASYNC16(sb + R_ATILE + sA,      gA1 + go);
        CP_ASYNC16(sb + R_ATILE + sA + 16, gA1 + go + 16);
        CP_ASYNC16(sb + 2 * R_ATILE + sB,           gB0 + go);
        CP_ASYNC16(sb + 2 * R_ATILE + R_BTILE + sB, gB1 + go);
        CP_COMMIT();
    };

    const uint32_t aRow = (uint32_t)(wm + (lid & 15)) * ROWB + (lid >> 4) * 16;
    const uint32_t bRow = (uint32_t)(wn + (lid & 7) + ((lid >> 4) & 1) * 8) * ROWB
                        + ((lid >> 3) & 1) * 16;

    load_stage(0, 0);
    load_stage(1, 1);
    load_stage(2, 2);

    for (int kt = 0; kt < R_KT; kt++) {
        if (kt < R_KT - 2) {
            asm volatile("cp.async.wait_group 2;" ::: "memory");
        } else {
            asm volatile("cp.async.wait_group 0;" ::: "memory");
        }
        __syncthreads();

        const uint32_t sb = sbase + (kt % R_NSTAGE) * R_STAGE;
#pragma unroll
        for (int k16 = 0; k16 < 2; k16++) {
            const uint32_t kOff = k16 * 32;
            uint32_t b0[2][4], b1f[2][4];
#pragma unroll
            for (int nt2 = 0; nt2 < 2; nt2++) {
                ldsm_x4(b0[nt2],  sb + 2 * R_ATILE + bRow + kOff + nt2 * 16 * ROWB);
                ldsm_x4(b1f[nt2], sb + 2 * R_ATILE + R_BTILE + bRow + kOff + nt2 * 16 * ROWB);
            }
            uint32_t a0[2][4];
#pragma unroll
            for (int mt = 0; mt < 2; mt++)
                ldsm_x4(a0[mt], sb + aRow + kOff + mt * 16 * ROWB);
#pragma unroll
            for (int mt = 0; mt < 2; mt++) {
#pragma unroll
                for (int nt = 0; nt < 4; nt++) {
                    const int n2 = nt >> 1, h = (nt & 1) * 2;
                    mma16816(acc[mt][nt], a0[mt], b0[n2][h],  b0[n2][h + 1]);
                    mma16816(acc[mt][nt], a0[mt], b1f[n2][h], b1f[n2][h + 1]);
                }
            }
            uint32_t a1[2][4];
#pragma unroll
            for (int mt = 0; mt < 2; mt++)
                ldsm_x4(a1[mt], sb + R_ATILE + aRow + kOff + mt * 16 * ROWB);
#pragma unroll
            for (int mt = 0; mt < 2; mt++) {
#pragma unroll
                for (int nt = 0; nt < 4; nt++) {
                    const int n2 = nt >> 1, h = (nt & 1) * 2;
                    mma16816(acc[mt][nt], a1[mt], b0[n2][h], b0[n2][h + 1]);
                }
            }
        }
        __syncthreads();
        if (kt + R_NSTAGE < R_KT) load_stage(kt % R_NSTAGE, kt + R_NSTAGE);
    }

    // write logits (+bias) into smem
    {
        const int g = lid >> 2;
        const int i2 = (lid & 3) * 2;
#pragma unroll
        for (int nt = 0; nt < 4; nt++) {
            const int col = wn + nt * 8 + i2;
            const float bx = b2[col], by = b2[col + 1];
#pragma unroll
            for (int mt = 0; mt < 2; mt++) {
                const int row = wm + mt * 16 + g;
                *reinterpret_cast<float2*>(&lg[row * LGS + col]) =
                    make_float2(acc[mt][nt][0] + bx, acc[mt][nt][1] + by);
                *reinterpret_cast<float2*>(&lg[(row + 8) * LGS + col]) =
                    make_float2(acc[mt][nt][2] + bx, acc[mt][nt][3] + by);
            }
        }
    }
    __syncthreads();

    // softmax + top-2 + small outputs: one thread per token
    if (tid < 128) {
        const int tok = tok0 + tid;
        float* row = &lg[tid * LGS];
        float mx = -1e30f;
#pragma unroll
        for (int e = 0; e < NEXP; e++) mx = fmaxf(mx, row[e]);
        float s = 0.f;
#pragma unroll
        for (int e = 0; e < NEXP; e++) {
            float ev = expf(row[e] - mx);
            row[e] = ev;
            s += ev;
        }
        float inv = 1.0f / s;
        sinv[tid] = inv;

        float v1 = -1.0f, v2 = -1.0f;
        int i1 = 0, i2v = 0;
#pragma unroll
        for (int e = NSHARED; e < NEXP; e++) {
            float v = row[e];
            if (v > v1)      { v2 = v1; i2v = i1; v1 = v; i1 = e; }
            else if (v > v2) { v2 = v;  i2v = e; }
        }
#pragma unroll
        for (int e = 0; e < NSHARED; e++)
            out[G_OFF + (size_t)tok * NSHARED + e] = row[e] * inv;
        out[LW_OFF + (size_t)tok * TOPK + 0] = v1 * inv;
        out[LW_OFF + (size_t)tok * TOPK + 1] = v2 * inv;
        out[LI_OFF + (size_t)tok * TOPK + 0] = (float)(i1 - NSHARED);
        out[LI_OFF + (size_t)tok * TOPK + 1] = (float)(i2v - NSHARED);
    }
    __syncthreads();

    // full weights matrix: 128 tokens x 32 float2 = 4096 float2, 16 per thread
#pragma unroll
    for (int hh = 0; hh < 16; hh++) {
        int f = tid + 256 * hh;
        int tr = f >> 5;
        int ec = (f & 31) * 2;
        float inv = sinv[tr];
        float2 v = *reinterpret_cast<const float2*>(&lg[tr * LGS + ec]);
        v.x *= inv; v.y *= inv;
        *reinterpret_cast<float2*>(
            &out[W_OFF + (size_t)(tok0 + tr) * NEXP + ec]) = v;
    }
}

// ---------------------------------------------------------------------------
extern "C" void kernel_launch(void* const* d_in, const int* in_sizes, int n_in,
                              void* d_out, int out_size) {
    const float* x  = (const float*)d_in[0];
    const float* W1 = (const float*)d_in[1];
    const float* b1 = (const float*)d_in[2];
    const float* W2 = (const float*)d_in[3];
    const float* b2 = (const float*)d_in[4];
    float* out = (float*)d_out;

    static int attr_done = 0;
    if (!attr_done) {
        cudaFuncSetAttribute(gemm1_hmma_kernel,
                             cudaFuncAttributeMaxDynamicSharedMemorySize, SMEM_GEMM);
        cudaFuncSetAttribute(router_hmma_kernel,
                             cudaFuncAttributeMaxDynamicSharedMemorySize, SMEM_ROUTER);
        attr_done = 1;
    }

    conv_x_kernel<<<(NTOK * DIN) / (256 * 4), 256>>>(x);
    conv_w1_kernel<<<dim3(HMID / 32, DIN / 32), dim3(32, 8)>>>(W1);
    conv_w2_kernel<<<dim3(NEXP / 32, HMID / 32), dim3(32, 8)>>>(W2);
    gemm1_hmma_kernel<<<dim3(HMID / 128, NTOK / 128), 256, SMEM_GEMM>>>(b1);
    router_hmma_kernel<<<NTOK / 128, 256, SMEM_ROUTER>>>(b2, out);
}

// round 6
// speedup vs baseline: 2.6246x; 1.0896x over previous
#include <cuda_runtime.h>
#include <cuda_fp16.h>
#include <math.h>
#include <stdint.h>

// ---------------------------------------------------------------------------
// Problem constants
// ---------------------------------------------------------------------------
#define NTOK  16384
#define DIN   2048
#define HMID  4096
#define NEXP  64
#define NSHARED 8
#define TOPK  2

// Output layout (flattened concat of the reference tuple)
#define G_OFF  0
#define LW_OFF (NTOK * NSHARED)
#define LI_OFF (LW_OFF + NTOK * TOPK)
#define W_OFF  (LI_OFF + NTOK * TOPK)

// ---------------------------------------------------------------------------
// Scratch (static device arrays; no allocation)
// ---------------------------------------------------------------------------
__device__ __half g_x0[(size_t)NTOK * DIN];           // x limb planes
__device__ __half g_x1[(size_t)NTOK * DIN];
__device__ __half g_w0[(size_t)HMID * DIN];           // W1^T limb planes
__device__ __half g_w1[(size_t)HMID * DIN];
__device__ __half g_h0[(size_t)NTOK * HMID];          // h limb planes
__device__ __half g_h1[(size_t)NTOK * HMID];
__device__ __half g_u0[(size_t)NEXP * HMID];          // W2^T limb planes
__device__ __half g_u1[(size_t)NEXP * HMID];

__device__ __forceinline__ uint32_t smem_u32(const void* p) {
    uint32_t a;
    asm("{ .reg .u64 t; cvta.to.shared.u64 t, %1; cvt.u32.u64 %0, t; }"
        : "=r"(a) : "l"(p));
    return a;
}

__device__ __forceinline__ float gelu_exact(float v) {
    return 0.5f * v * (1.0f + erff(v * 0.70710678118654752440f));
}

__device__ __forceinline__ void ldsm_x4(uint32_t* r, uint32_t addr) {
    asm volatile("ldmatrix.sync.aligned.m8n8.x4.shared.b16 {%0,%1,%2,%3}, [%4];"
                 : "=r"(r[0]), "=r"(r[1]), "=r"(r[2]), "=r"(r[3]) : "r"(addr));
}

__device__ __forceinline__ void mma16816(float* d, const uint32_t* a,
                                         uint32_t b0, uint32_t b1) {
    asm volatile(
        "mma.sync.aligned.m16n8k16.row.col.f32.f16.f16.f32 "
        "{%0,%1,%2,%3}, {%4,%5,%6,%7}, {%8,%9}, {%0,%1,%2,%3};"
        : "+f"(d[0]), "+f"(d[1]), "+f"(d[2]), "+f"(d[3])
        : "r"(a[0]), "r"(a[1]), "r"(a[2]), "r"(a[3]), "r"(b0), "r"(b1));
}

#define CP_ASYNC16(dst, src) \
    asm volatile("cp.async.cg.shared.global [%0], [%1], 16;" \
                 :: "r"(dst), "l"(src) : "memory")
#define CP_COMMIT() asm volatile("cp.async.commit_group;" ::: "memory")

__device__ __forceinline__ uint32_t pack_limbs(float x, float y,
                                               float& rx, float& ry) {
    __half hx = __float2half_rn(x), hy = __float2half_rn(y);
    rx = x - __half2float(hx);
    ry = y - __half2float(hy);
    return (uint32_t)__half_as_ushort(hx) | ((uint32_t)__half_as_ushort(hy) << 16);
}

// ---------------------------------------------------------------------------
// conv_x: split x into 2 fp16 limb planes (row-major, K contiguous)
// ---------------------------------------------------------------------------
__global__ void __launch_bounds__(256)
conv_x_kernel(const float* __restrict__ x) {
    size_t i = ((size_t)blockIdx.x * 256 + threadIdx.x) * 4;
    float4 v = *reinterpret_cast<const float4*>(&x[i]);
    float a[4] = {v.x, v.y, v.z, v.w};
    unsigned short u0[4], u1[4];
#pragma unroll
    for (int j = 0; j < 4; j++) {
        __half h0 = __float2half_rn(a[j]);
        float r = a[j] - __half2float(h0);
        __half h1 = __float2half_rn(r);
        u0[j] = __half_as_ushort(h0);
        u1[j] = __half_as_ushort(h1);
    }
    *reinterpret_cast<uint2*>(&g_x0[i]) =
        make_uint2((uint32_t)u0[0] | ((uint32_t)u0[1] << 16),
                   (uint32_t)u0[2] | ((uint32_t)u0[3] << 16));
    *reinterpret_cast<uint2*>(&g_x1[i]) =
        make_uint2((uint32_t)u1[0] | ((uint32_t)u1[1] << 16),
                   (uint32_t)u1[2] | ((uint32_t)u1[3] << 16));
}

// ---------------------------------------------------------------------------
// conv_w1: transpose W1 [K,N] -> [N,K], split into 2 fp16 limb planes
// ---------------------------------------------------------------------------
__global__ void __launch_bounds__(256)
conv_w1_kernel(const float* __restrict__ W1) {
    __shared__ float tile[32][33];
    const int tx = threadIdx.x, ty = threadIdx.y;
    const int n0 = blockIdx.x * 32;
    const int k0 = blockIdx.y * 32;
#pragma unroll
    for (int j = 0; j < 4; j++)
        tile[ty + j * 8][tx] = W1[(size_t)(k0 + ty + j * 8) * HMID + n0 + tx];
    __syncthreads();
#pragma unroll
    for (int j = 0; j < 4; j++) {
        float v = tile[tx][ty + j * 8];
        __half h0 = __float2half_rn(v);
        float r = v - __half2float(h0);
        size_t o = (size_t)(n0 + ty + j * 8) * DIN + k0 + tx;
        g_w0[o] = h0;
        g_w1[o] = __float2half_rn(r);
    }
}

// ---------------------------------------------------------------------------
// conv_w2: transpose W2 [K=4096, 64] -> [64][4096], split into 2 limb planes
// ---------------------------------------------------------------------------
__global__ void __launch_bounds__(256)
conv_w2_kernel(const float* __restrict__ W2) {
    __shared__ float tile[32][33];
    const int tx = threadIdx.x, ty = threadIdx.y;
    const int n0 = blockIdx.x * 32;
    const int k0 = blockIdx.y * 32;
#pragma unroll
    for (int j = 0; j < 4; j++)
        tile[ty + j * 8][tx] = W2[(size_t)(k0 + ty + j * 8) * NEXP + n0 + tx];
    __syncthreads();
#pragma unroll
    for (int j = 0; j < 4; j++) {
        float v = tile[tx][ty + j * 8];
        __half h0 = __float2half_rn(v);
        float r = v - __half2float(h0);
        size_t o = (size_t)(n0 + ty + j * 8) * HMID + k0 + tx;
        g_u0[o] = h0;
        g_u1[o] = __float2half_rn(r);
    }
}

// ---------------------------------------------------------------------------
// gemm1: h = gelu(x @ W1 + b1) via mma.sync fp16 2-limb, 3 products.
// CTA 128x128, K-chunk 32, SW64-swizzled 64B rows, 3-stage cp.async pipeline,
// single barrier per k-step, loads lead compute by 2 stages. 2 CTAs/SM.
// ---------------------------------------------------------------------------
#define TILE64  (128 * 64)             // 8192 bytes per limb tile
#define STAGE64 (4 * TILE64)           // 32768
#define GSTAGES 3
#define SMEM_GEMM (GSTAGES * STAGE64)  // 98304
#define KT (DIN / 32)                  // 64

__global__ void __launch_bounds__(256, 2)
gemm1_hmma_kernel(const float* __restrict__ b1) {
    extern __shared__ char smem[];
    const uint32_t sbase = smem_u32(smem);
    const int tid = threadIdx.x;
    const int wid = tid >> 5;
    const int lid = tid & 31;
    const int row0 = blockIdx.y * 128;
    const int col0 = blockIdx.x * 128;
    const int wm = (wid >> 2) * 64;
    const int wn = (wid & 3) * 32;

    // ---- loader mapping: row lr = tid>>1, chunks cc..cc+1 of 4 (16B each) ----
    const int lr = tid >> 1;
    const int cc = (tid & 1) * 2;
    const int mS = (lr >> 1) & 3;
    const uint32_t dst0 = (uint32_t)lr * 64 + (uint32_t)(((cc)     ^ mS) << 4);
    const uint32_t dst1 = (uint32_t)lr * 64 + (uint32_t)(((cc + 1) ^ mS) << 4);
    const char* gA0 = (const char*)(g_x0 + (size_t)(row0 + lr) * DIN) + cc * 16;
    const char* gA1 = (const char*)(g_x1 + (size_t)(row0 + lr) * DIN) + cc * 16;
    const char* gB0 = (const char*)(g_w0 + (size_t)(col0 + lr) * DIN) + cc * 16;
    const char* gB1 = (const char*)(g_w1 + (size_t)(col0 + lr) * DIN) + cc * 16;

    float acc[4][4][4];
#pragma unroll
    for (int i = 0; i < 4; i++)
#pragma unroll
        for (int j = 0; j < 4; j++)
#pragma unroll
            for (int k = 0; k < 4; k++) acc[i][j][k] = 0.f;

    auto load_stage = [&](int s, int kt) {
        const uint32_t sb = sbase + s * STAGE64;
        const int go = kt * 64;
        CP_ASYNC16(sb + dst0,              gA0 + go);
        CP_ASYNC16(sb + dst1,              gA0 + go + 16);
        CP_ASYNC16(sb + TILE64 + dst0,     gA1 + go);
        CP_ASYNC16(sb + TILE64 + dst1,     gA1 + go + 16);
        CP_ASYNC16(sb + 2 * TILE64 + dst0, gB0 + go);
        CP_ASYNC16(sb + 2 * TILE64 + dst1, gB0 + go + 16);
        CP_ASYNC16(sb + 3 * TILE64 + dst0, gB1 + go);
        CP_ASYNC16(sb + 3 * TILE64 + dst1, gB1 + go + 16);
        CP_COMMIT();
    };

    // ---- ldmatrix address components (swizzle masks are mt/nt invariant) ----
    const uint32_t aRowB = (uint32_t)(wm + (lid & 15)) * 64;
    const int cidxA = lid >> 4;
    const int mA = ((lid & 15) >> 1) & 3;
    const int brow = (lid & 7) + ((lid >> 4) & 1) * 8;
    const uint32_t bRowB = (uint32_t)(wn + brow) * 64;
    const int cidxB = (lid >> 3) & 1;
    const int mB = (brow >> 1) & 3;
    uint32_t aCol[2], bCol[2];
#pragma unroll
    for (int k16 = 0; k16 < 2; k16++) {
        aCol[k16] = (uint32_t)((((k16 << 1) | cidxA) ^ mA) << 4);
        bCol[k16] = (uint32_t)((((k16 << 1) | cidxB) ^ mB) << 4);
    }

    load_stage(0, 0);
    load_stage(1, 1);

    for (int kt = 0; kt < KT; kt++) {
        if (kt + 2 < KT) {
            asm volatile("cp.async.wait_group 1;" ::: "memory");
        } else {
            asm volatile("cp.async.wait_group 0;" ::: "memory");
        }
        __syncthreads();
        if (kt + 2 < KT) load_stage((kt + 2) % GSTAGES, kt + 2);

        const uint32_t sb = sbase + (kt % GSTAGES) * STAGE64;
#pragma unroll
        for (int k16 = 0; k16 < 2; k16++) {
            uint32_t b0[2][4], b1f[2][4];
#pragma unroll
            for (int nt2 = 0; nt2 < 2; nt2++) {
                const uint32_t bo = bRowB + nt2 * 1024 + bCol[k16];
                ldsm_x4(b0[nt2],  sb + 2 * TILE64 + bo);
                ldsm_x4(b1f[nt2], sb + 3 * TILE64 + bo);
            }
            uint32_t a0[4][4];
#pragma unroll
            for (int mt = 0; mt < 4; mt++)
                ldsm_x4(a0[mt], sb + aRowB + mt * 1024 + aCol[k16]);
#pragma unroll
            for (int mt = 0; mt < 4; mt++) {
#pragma unroll
                for (int nt = 0; nt < 4; nt++) {
                    const int n2 = nt >> 1, h = (nt & 1) * 2;
                    mma16816(acc[mt][nt], a0[mt], b0[n2][h],  b0[n2][h + 1]);
                    mma16816(acc[mt][nt], a0[mt], b1f[n2][h], b1f[n2][h + 1]);
                }
            }
            uint32_t a1[4][4];
#pragma unroll
            for (int mt = 0; mt < 4; mt++)
                ldsm_x4(a1[mt], sb + TILE64 + aRowB + mt * 1024 + aCol[k16]);
#pragma unroll
            for (int mt = 0; mt < 4; mt++) {
#pragma unroll
                for (int nt = 0; nt < 4; nt++) {
                    const int n2 = nt >> 1, h = (nt & 1) * 2;
                    mma16816(acc[mt][nt], a1[mt], b0[n2][h], b0[n2][h + 1]);
                }
            }
        }
    }

    // epilogue: bias + gelu + split into fp16 limbs + store
    const int g = lid >> 2;
    const int i2 = (lid & 3) * 2;
#pragma unroll
    for (int nt = 0; nt < 4; nt++) {
        const int col = col0 + wn + nt * 8 + i2;
        const float bx = b1[col], by = b1[col + 1];
#pragma unroll
        for (int mt = 0; mt < 4; mt++) {
            const int row = row0 + wm + mt * 16 + g;
            float lox = gelu_exact(acc[mt][nt][0] + bx);
            float loy = gelu_exact(acc[mt][nt][1] + by);
            float hix = gelu_exact(acc[mt][nt][2] + bx);
            float hiy = gelu_exact(acc[mt][nt][3] + by);
            float r0, r1, r2, r3;
            uint32_t p0 = pack_limbs(lox, loy, r0, r1);
            uint32_t p1 = pack_limbs(hix, hiy, r2, r3);
            size_t o0 = (size_t)row * HMID + col;
            size_t o1 = (size_t)(row + 8) * HMID + col;
            *reinterpret_cast<uint32_t*>(&g_h0[o0]) = p0;
            *reinterpret_cast<uint32_t*>(&g_h0[o1]) = p1;
            __half q0 = __float2half_rn(r0), q1 = __float2half_rn(r1);
            __half q2 = __float2half_rn(r2), q3 = __float2half_rn(r3);
            *reinterpret_cast<uint32_t*>(&g_h1[o0]) =
                (uint32_t)__half_as_ushort(q0) | ((uint32_t)__half_as_ushort(q1) << 16);
            *reinterpret_cast<uint32_t*>(&g_h1[o1]) =
                (uint32_t)__half_as_ushort(q2) | ((uint32_t)__half_as_ushort(q3) << 16);
        }
    }
}

// ---------------------------------------------------------------------------
// router: logits = h @ W2 + b2 via HMMA (2-limb, 3 products), then softmax,
// shared/local split, top-2, all outputs. CTA = 128 tokens x 64 experts.
// Single barrier per k-step, loads lead compute by 2 stages.
// ---------------------------------------------------------------------------
#define ROWB 80
#define R_ATILE (128 * ROWB)                 // 10240 per limb
#define R_BTILE (64 * ROWB)                  // 5120 per limb
#define R_STAGE (2 * R_ATILE + 2 * R_BTILE)  // 30720
#define R_NSTAGE 3
#define R_KT (HMID / 32)                     // 128
#define LGS 66
#define SMEM_ROUTER (R_NSTAGE * R_STAGE + 128 * LGS * 4 + 512)   // 126464

__global__ void __launch_bounds__(256)
router_hmma_kernel(const float* __restrict__ b2, float* __restrict__ out) {
    extern __shared__ char smem[];
    const uint32_t sbase = smem_u32(smem);
    float* lg   = reinterpret_cast<float*>(smem + R_NSTAGE * R_STAGE);
    float* sinv = lg + 128 * LGS;

    const int tid = threadIdx.x;
    const int wid = tid >> 5;
    const int lid = tid & 31;
    const int tok0 = blockIdx.x * 128;
    const int wm = (wid >> 1) * 32;
    const int wn = (wid & 1) * 32;

    const int lr  = tid >> 1;
    const int cc  = (tid & 1) * 2;
    const char* gA0 = (const char*)(g_h0 + (size_t)(tok0 + lr) * HMID) + cc * 16;
    const char* gA1 = (const char*)(g_h1 + (size_t)(tok0 + lr) * HMID) + cc * 16;
    const uint32_t sA = (uint32_t)lr * ROWB + cc * 16;
    const int br = tid >> 2;
    const int bc = tid & 3;
    const char* gB0 = (const char*)(g_u0 + (size_t)br * HMID) + bc * 16;
    const char* gB1 = (const char*)(g_u1 + (size_t)br * HMID) + bc * 16;
    const uint32_t sB = (uint32_t)br * ROWB + bc * 16;

    float acc[2][4][4];
#pragma unroll
    for (int i = 0; i < 2; i++)
#pragma unroll
        for (int j = 0; j < 4; j++)
#pragma unroll
            for (int k = 0; k < 4; k++) acc[i][j][k] = 0.f;

    auto load_stage = [&](int s, int kt) {
        const uint32_t sb = sbase + s * R_STAGE;
        const int go = kt * 64;
        CP_ASYNC16(sb + sA,      gA0 + go);
        CP_ASYNC16(sb + sA + 16, gA0 + go + 16);
        CP_ASYNC16(sb + R_ATILE + sA,      gA1 + go);
        CP_ASYNC16(sb + R_ATILE + sA + 16, gA1 + go + 16);
        CP_ASYNC16(sb + 2 * R_ATILE + sB,           gB0 + go);
        CP_ASYNC16(sb + 2 * R_ATILE + R_BTILE + sB, gB1 + go);
        CP_COMMIT();
    };

    const uint32_t aRow = (uint32_t)(wm + (lid & 15)) * ROWB + (lid >> 4) * 16;
    const uint32_t bRow = (uint32_t)(wn + (lid & 7) + ((lid >> 4) & 1) * 8) * ROWB
                        + ((lid >> 3) & 1) * 16;

    load_stage(0, 0);
    load_stage(1, 1);

    for (int kt = 0; kt < R_KT; kt++) {
        if (kt + 2 < R_KT) {
            asm volatile("cp.async.wait_group 1;" ::: "memory");
        } else {
            asm volatile("cp.async.wait_group 0;" ::: "memory");
        }
        __syncthreads();
        if (kt + 2 < R_KT) load_stage((kt + 2) % R_NSTAGE, kt + 2);

        const uint32_t sb = sbase + (kt % R_NSTAGE) * R_STAGE;
#pragma unroll
        for (int k16 = 0; k16 < 2; k16++) {
            const uint32_t kOff = k16 * 32;
            uint32_t b0[2][4], b1f[2][4];
#pragma unroll
            for (int nt2 = 0; nt2 < 2; nt2++) {
                ldsm_x4(b0[nt2],  sb + 2 * R_ATILE + bRow + kOff + nt2 * 16 * ROWB);
                ldsm_x4(b1f[nt2], sb + 2 * R_ATILE + R_BTILE + bRow + kOff + nt2 * 16 * ROWB);
            }
            uint32_t a0[2][4];
#pragma unroll
            for (int mt = 0; mt < 2; mt++)
                ldsm_x4(a0[mt], sb + aRow + kOff + mt * 16 * ROWB);
#pragma unroll
            for (int mt = 0; mt < 2; mt++) {
#pragma unroll
                for (int nt = 0; nt < 4; nt++) {
                    const int n2 = nt >> 1, h = (nt & 1) * 2;
                    mma16816(acc[mt][nt], a0[mt], b0[n2][h],  b0[n2][h + 1]);
                    mma16816(acc[mt][nt], a0[mt], b1f[n2][h], b1f[n2][h + 1]);
                }
            }
            uint32_t a1[2][4];
#pragma unroll
            for (int mt = 0; mt < 2; mt++)
                ldsm_x4(a1[mt], sb + R_ATILE + aRow + kOff + mt * 16 * ROWB);
#pragma unroll
            for (int mt = 0; mt < 2; mt++) {
#pragma unroll
                for (int nt = 0; nt < 4; nt++) {
                    const int n2 = nt >> 1, h = (nt & 1) * 2;
                    mma16816(acc[mt][nt], a1[mt], b0[n2][h], b0[n2][h + 1]);
                }
            }
        }
    }

    // write logits (+bias) into smem
    {
        const int g = lid >> 2;
        const int i2 = (lid & 3) * 2;
#pragma unroll
        for (int nt = 0; nt < 4; nt++) {
            const int col = wn + nt * 8 + i2;
            const float bx = b2[col], by = b2[col + 1];
#pragma unroll
            for (int mt = 0; mt < 2; mt++) {
                const int row = wm + mt * 16 + g;
                *reinterpret_cast<float2*>(&lg[row * LGS + col]) =
                    make_float2(acc[mt][nt][0] + bx, acc[mt][nt][1] + by);
                *reinterpret_cast<float2*>(&lg[(row + 8) * LGS + col]) =
                    make_float2(acc[mt][nt][2] + bx, acc[mt][nt][3] + by);
            }
        }
    }
    __syncthreads();

    // softmax + top-2 + small outputs: one thread per token
    if (tid < 128) {
        const int tok = tok0 + tid;
        float* row = &lg[tid * LGS];
        float mx = -1e30f;
#pragma unroll
        for (int e = 0; e < NEXP; e++) mx = fmaxf(mx, row[e]);
        float s = 0.f;
#pragma unroll
        for (int e = 0; e < NEXP; e++) {
            float ev = expf(row[e] - mx);
            row[e] = ev;
            s += ev;
        }
        float inv = 1.0f / s;
        sinv[tid] = inv;

        float v1 = -1.0f, v2 = -1.0f;
        int i1 = 0, i2v = 0;
#pragma unroll
        for (int e = NSHARED; e < NEXP; e++) {
            float v = row[e];
            if (v > v1)      { v2 = v1; i2v = i1; v1 = v; i1 = e; }
            else if (v > v2) { v2 = v;  i2v = e; }
        }
#pragma unroll
        for (int e = 0; e < NSHARED; e++)
            out[G_OFF + (size_t)tok * NSHARED + e] = row[e] * inv;
        out[LW_OFF + (size_t)tok * TOPK + 0] = v1 * inv;
        out[LW_OFF + (size_t)tok * TOPK + 1] = v2 * inv;
        out[LI_OFF + (size_t)tok * TOPK + 0] = (float)(i1 - NSHARED);
        out[LI_OFF + (size_t)tok * TOPK + 1] = (float)(i2v - NSHARED);
    }
    __syncthreads();

    // full weights matrix: 128 tokens x 32 float2 = 4096 float2, 16 per thread
#pragma unroll
    for (int hh = 0; hh < 16; hh++) {
        int f = tid + 256 * hh;
        int tr = f >> 5;
        int ec = (f & 31) * 2;
        float inv = sinv[tr];
        float2 v = *reinterpret_cast<const float2*>(&lg[tr * LGS + ec]);
        v.x *= inv; v.y *= inv;
        *reinterpret_cast<float2*>(
            &out[W_OFF + (size_t)(tok0 + tr) * NEXP + ec]) = v;
    }
}

// ---------------------------------------------------------------------------
extern "C" void kernel_launch(void* const* d_in, const int* in_sizes, int n_in,
                              void* d_out, int out_size) {
    const float* x  = (const float*)d_in[0];
    const float* W1 = (const float*)d_in[1];
    const float* b1 = (const float*)d_in[2];
    const float* W2 = (const float*)d_in[3];
    const float* b2 = (const float*)d_in[4];
    float* out = (float*)d_out;

    static int attr_done = 0;
    if (!attr_done) {
        cudaFuncSetAttribute(gemm1_hmma_kernel,
                             cudaFuncAttributeMaxDynamicSharedMemorySize, SMEM_GEMM);
        cudaFuncSetAttribute(router_hmma_kernel,
                             cudaFuncAttributeMaxDynamicSharedMemorySize, SMEM_ROUTER);
        attr_done = 1;
    }

    conv_x_kernel<<<(NTOK * DIN) / (256 * 4), 256>>>(x);
    conv_w1_kernel<<<dim3(HMID / 32, DIN / 32), dim3(32, 8)>>>(W1);
    conv_w2_kernel<<<dim3(NEXP / 32, HMID / 32), dim3(32, 8)>>>(W2);
    gemm1_hmma_kernel<<<dim3(HMID / 128, NTOK / 128), 256, SMEM_GEMM>>>(b1);
    router_hmma_kernel<<<NTOK / 128, 256, SMEM_ROUTER>>>(b2, out);
}

// round 7
// speedup vs baseline: 2.6335x; 1.0034x over previous
#include <cuda_runtime.h>
#include <cuda_fp16.h>
#include <math.h>
#include <stdint.h>

// ---------------------------------------------------------------------------
// Problem constants
// ---------------------------------------------------------------------------
#define NTOK  16384
#define DIN   2048
#define HMID  4096
#define NEXP  64
#define NSHARED 8
#define TOPK  2

// Output layout (flattened concat of the reference tuple)
#define G_OFF  0
#define LW_OFF (NTOK * NSHARED)
#define LI_OFF (LW_OFF + NTOK * TOPK)
#define W_OFF  (LI_OFF + NTOK * TOPK)

// ---------------------------------------------------------------------------
// Scratch (static device arrays; no allocation)
// ---------------------------------------------------------------------------
__device__ __half g_x0[(size_t)NTOK * DIN];           // x limb planes
__device__ __half g_x1[(size_t)NTOK * DIN];
__device__ __half g_w0[(size_t)HMID * DIN];           // W1^T limb planes
__device__ __half g_w1[(size_t)HMID * DIN];
__device__ __half g_h0[(size_t)NTOK * HMID];          // h limb planes
__device__ __half g_h1[(size_t)NTOK * HMID];
__device__ __half g_u0[(size_t)NEXP * HMID];          // W2^T limb planes
__device__ __half g_u1[(size_t)NEXP * HMID];

__device__ __forceinline__ uint32_t smem_u32(const void* p) {
    uint32_t a;
    asm("{ .reg .u64 t; cvta.to.shared.u64 t, %1; cvt.u32.u64 %0, t; }"
        : "=r"(a) : "l"(p));
    return a;
}

__device__ __forceinline__ float gelu_exact(float v) {
    return 0.5f * v * (1.0f + erff(v * 0.70710678118654752440f));
}

__device__ __forceinline__ void ldsm_x4(uint32_t* r, uint32_t addr) {
    asm volatile("ldmatrix.sync.aligned.m8n8.x4.shared.b16 {%0,%1,%2,%3}, [%4];"
                 : "=r"(r[0]), "=r"(r[1]), "=r"(r[2]), "=r"(r[3]) : "r"(addr));
}

__device__ __forceinline__ void mma16816(float* d, const uint32_t* a,
                                         uint32_t b0, uint32_t b1) {
    asm volatile(
        "mma.sync.aligned.m16n8k16.row.col.f32.f16.f16.f32 "
        "{%0,%1,%2,%3}, {%4,%5,%6,%7}, {%8,%9}, {%0,%1,%2,%3};"
        : "+f"(d[0]), "+f"(d[1]), "+f"(d[2]), "+f"(d[3])
        : "r"(a[0]), "r"(a[1]), "r"(a[2]), "r"(a[3]), "r"(b0), "r"(b1));
}

#define CP_ASYNC16(dst, src) \
    asm volatile("cp.async.cg.shared.global [%0], [%1], 16;" \
                 :: "r"(dst), "l"(src) : "memory")
#define CP_COMMIT() asm volatile("cp.async.commit_group;" ::: "memory")

__device__ __forceinline__ uint32_t pack_limbs(float x, float y,
                                               float& rx, float& ry) {
    __half hx = __float2half_rn(x), hy = __float2half_rn(y);
    rx = x - __half2float(hx);
    ry = y - __half2float(hy);
    return (uint32_t)__half_as_ushort(hx) | ((uint32_t)__half_as_ushort(hy) << 16);
}

// ---------------------------------------------------------------------------
// conv_x: split x into 2 fp16 limb planes (row-major, K contiguous)
// ---------------------------------------------------------------------------
__global__ void __launch_bounds__(256)
conv_x_kernel(const float* __restrict__ x) {
    size_t i = ((size_t)blockIdx.x * 256 + threadIdx.x) * 4;
    float4 v = *reinterpret_cast<const float4*>(&x[i]);
    float a[4] = {v.x, v.y, v.z, v.w};
    unsigned short u0[4], u1[4];
#pragma unroll
    for (int j = 0; j < 4; j++) {
        __half h0 = __float2half_rn(a[j]);
        float r = a[j] - __half2float(h0);
        __half h1 = __float2half_rn(r);
        u0[j] = __half_as_ushort(h0);
        u1[j] = __half_as_ushort(h1);
    }
    *reinterpret_cast<uint2*>(&g_x0[i]) =
        make_uint2((uint32_t)u0[0] | ((uint32_t)u0[1] << 16),
                   (uint32_t)u0[2] | ((uint32_t)u0[3] << 16));
    *reinterpret_cast<uint2*>(&g_x1[i]) =
        make_uint2((uint32_t)u1[0] | ((uint32_t)u1[1] << 16),
                   (uint32_t)u1[2] | ((uint32_t)u1[3] << 16));
}

// ---------------------------------------------------------------------------
// conv_w1: transpose W1 [K,N] -> [N,K], split into 2 fp16 limb planes
// ---------------------------------------------------------------------------
__global__ void __launch_bounds__(256)
conv_w1_kernel(const float* __restrict__ W1) {
    __shared__ float tile[32][33];
    const int tx = threadIdx.x, ty = threadIdx.y;
    const int n0 = blockIdx.x * 32;
    const int k0 = blockIdx.y * 32;
#pragma unroll
    for (int j = 0; j < 4; j++)
        tile[ty + j * 8][tx] = W1[(size_t)(k0 + ty + j * 8) * HMID + n0 + tx];
    __syncthreads();
#pragma unroll
    for (int j = 0; j < 4; j++) {
        float v = tile[tx][ty + j * 8];
        __half h0 = __float2half_rn(v);
        float r = v - __half2float(h0);
        size_t o = (size_t)(n0 + ty + j * 8) * DIN + k0 + tx;
        g_w0[o] = h0;
        g_w1[o] = __float2half_rn(r);
    }
}

// ---------------------------------------------------------------------------
// conv_w2: transpose W2 [K=4096, 64] -> [64][4096], split into 2 limb planes
// ---------------------------------------------------------------------------
__global__ void __launch_bounds__(256)
conv_w2_kernel(const float* __restrict__ W2) {
    __shared__ float tile[32][33];
    const int tx = threadIdx.x, ty = threadIdx.y;
    const int n0 = blockIdx.x * 32;
    const int k0 = blockIdx.y * 32;
#pragma unroll
    for (int j = 0; j < 4; j++)
        tile[ty + j * 8][tx] = W2[(size_t)(k0 + ty + j * 8) * NEXP + n0 + tx];
    __syncthreads();
#pragma unroll
    for (int j = 0; j < 4; j++) {
        float v = tile[tx][ty + j * 8];
        __half h0 = __float2half_rn(v);
        float r = v - __half2float(h0);
        size_t o = (size_t)(n0 + ty + j * 8) * HMID + k0 + tx;
        g_u0[o] = h0;
        g_u1[o] = __float2half_rn(r);
    }
}

// ---------------------------------------------------------------------------
// gemm1: h = gelu(x @ W1 + b1) via mma.sync fp16 2-limb, 3 products.
// CTA 128x128, K-chunk 32, SW64-swizzled 64B rows, 3-stage cp.async pipeline.
// All LDSM hoisted to the top of each k16; MMAs issued product-major
// (same-acc reuse distance = 16); next-stage loads issued mid-iteration.
// ---------------------------------------------------------------------------
#define TILE64  (128 * 64)             // 8192 bytes per limb tile
#define STAGE64 (4 * TILE64)           // 32768
#define GSTAGES 3
#define SMEM_GEMM (GSTAGES * STAGE64)  // 98304
#define KT (DIN / 32)                  // 64

__global__ void __launch_bounds__(256, 2)
gemm1_hmma_kernel(const float* __restrict__ b1) {
    extern __shared__ char smem[];
    const uint32_t sbase = smem_u32(smem);
    const int tid = threadIdx.x;
    const int wid = tid >> 5;
    const int lid = tid & 31;
    const int row0 = blockIdx.y * 128;
    const int col0 = blockIdx.x * 128;
    const int wm = (wid >> 2) * 64;
    const int wn = (wid & 3) * 32;

    // ---- loader mapping: row lr = tid>>1, chunks cc..cc+1 of 4 (16B each) ----
    const int lr = tid >> 1;
    const int cc = (tid & 1) * 2;
    const int mS = (lr >> 1) & 3;
    const uint32_t dst0 = (uint32_t)lr * 64 + (uint32_t)(((cc)     ^ mS) << 4);
    const uint32_t dst1 = (uint32_t)lr * 64 + (uint32_t)(((cc + 1) ^ mS) << 4);
    const char* gA0 = (const char*)(g_x0 + (size_t)(row0 + lr) * DIN) + cc * 16;
    const char* gA1 = (const char*)(g_x1 + (size_t)(row0 + lr) * DIN) + cc * 16;
    const char* gB0 = (const char*)(g_w0 + (size_t)(col0 + lr) * DIN) + cc * 16;
    const char* gB1 = (const char*)(g_w1 + (size_t)(col0 + lr) * DIN) + cc * 16;

    float acc[4][4][4];
#pragma unroll
    for (int i = 0; i < 4; i++)
#pragma unroll
        for (int j = 0; j < 4; j++)
#pragma unroll
            for (int k = 0; k < 4; k++) acc[i][j][k] = 0.f;

    auto load_stage = [&](int s, int kt) {
        const uint32_t sb = sbase + s * STAGE64;
        const int go = kt * 64;
        CP_ASYNC16(sb + dst0,              gA0 + go);
        CP_ASYNC16(sb + dst1,              gA0 + go + 16);
        CP_ASYNC16(sb + TILE64 + dst0,     gA1 + go);
        CP_ASYNC16(sb + TILE64 + dst1,     gA1 + go + 16);
        CP_ASYNC16(sb + 2 * TILE64 + dst0, gB0 + go);
        CP_ASYNC16(sb + 2 * TILE64 + dst1, gB0 + go + 16);
        CP_ASYNC16(sb + 3 * TILE64 + dst0, gB1 + go);
        CP_ASYNC16(sb + 3 * TILE64 + dst1, gB1 + go + 16);
        CP_COMMIT();
    };

    // ---- ldmatrix address components (swizzle masks are mt/nt invariant) ----
    const uint32_t aRowB = (uint32_t)(wm + (lid & 15)) * 64;
    const int cidxA = lid >> 4;
    const int mA = ((lid & 15) >> 1) & 3;
    const int brow = (lid & 7) + ((lid >> 4) & 1) * 8;
    const uint32_t bRowB = (uint32_t)(wn + brow) * 64;
    const int cidxB = (lid >> 3) & 1;
    const int mB = (brow >> 1) & 3;
    uint32_t aCol[2], bCol[2];
#pragma unroll
    for (int k16 = 0; k16 < 2; k16++) {
        aCol[k16] = (uint32_t)((((k16 << 1) | cidxA) ^ mA) << 4);
        bCol[k16] = (uint32_t)((((k16 << 1) | cidxB) ^ mB) << 4);
    }

    load_stage(0, 0);
    load_stage(1, 1);

    for (int kt = 0; kt < KT; kt++) {
        if (kt < KT - 1) {
            asm volatile("cp.async.wait_group 1;" ::: "memory");
        } else {
            asm volatile("cp.async.wait_group 0;" ::: "memory");
        }
        __syncthreads();

        const uint32_t sb = sbase + (kt % GSTAGES) * STAGE64;
#pragma unroll
        for (int k16 = 0; k16 < 2; k16++) {
            // ---- all fragment loads first ----
            uint32_t b0[2][4], b1f[2][4];
#pragma unroll
            for (int nt2 = 0; nt2 < 2; nt2++) {
                const uint32_t bo = bRowB + nt2 * 1024 + bCol[k16];
                ldsm_x4(b0[nt2],  sb + 2 * TILE64 + bo);
                ldsm_x4(b1f[nt2], sb + 3 * TILE64 + bo);
            }
            uint32_t a0[4][4], a1[4][4];
#pragma unroll
            for (int mt = 0; mt < 4; mt++)
                ldsm_x4(a0[mt], sb + aRowB + mt * 1024 + aCol[k16]);
#pragma unroll
            for (int mt = 0; mt < 4; mt++)
                ldsm_x4(a1[mt], sb + TILE64 + aRowB + mt * 1024 + aCol[k16]);

            // ---- product-major MMA issue (same-acc distance = 16) ----
#pragma unroll
            for (int mt = 0; mt < 4; mt++)
#pragma unroll
                for (int nt = 0; nt < 4; nt++) {
                    const int n2 = nt >> 1, h = (nt & 1) * 2;
                    mma16816(acc[mt][nt], a0[mt], b0[n2][h], b0[n2][h + 1]);
                }
            // spread next-stage global loads into the MMA stream (k16==0 only)
            if (k16 == 0 && kt + 2 < KT)
                load_stage((kt + 2) % GSTAGES, kt + 2);
#pragma unroll
            for (int mt = 0; mt < 4; mt++)
#pragma unroll
                for (int nt = 0; nt < 4; nt++) {
                    const int n2 = nt >> 1, h = (nt & 1) * 2;
                    mma16816(acc[mt][nt], a0[mt], b1f[n2][h], b1f[n2][h + 1]);
                }
#pragma unroll
            for (int mt = 0; mt < 4; mt++)
#pragma unroll
                for (int nt = 0; nt < 4; nt++) {
                    const int n2 = nt >> 1, h = (nt & 1) * 2;
                    mma16816(acc[mt][nt], a1[mt], b0[n2][h], b0[n2][h + 1]);
                }
        }
    }

    // epilogue: bias + gelu + split into fp16 limbs + store
    const int g = lid >> 2;
    const int i2 = (lid & 3) * 2;
#pragma unroll
    for (int nt = 0; nt < 4; nt++) {
        const int col = col0 + wn + nt * 8 + i2;
        const float bx = b1[col], by = b1[col + 1];
#pragma unroll
        for (int mt = 0; mt < 4; mt++) {
            const int row = row0 + wm + mt * 16 + g;
            float lox = gelu_exact(acc[mt][nt][0] + bx);
            float loy = gelu_exact(acc[mt][nt][1] + by);
            float hix = gelu_exact(acc[mt][nt][2] + bx);
            float hiy = gelu_exact(acc[mt][nt][3] + by);
            float r0, r1, r2, r3;
            uint32_t p0 = pack_limbs(lox, loy, r0, r1);
            uint32_t p1 = pack_limbs(hix, hiy, r2, r3);
            size_t o0 = (size_t)row * HMID + col;
            size_t o1 = (size_t)(row + 8) * HMID + col;
            *reinterpret_cast<uint32_t*>(&g_h0[o0]) = p0;
            *reinterpret_cast<uint32_t*>(&g_h0[o1]) = p1;
            __half q0 = __float2half_rn(r0), q1 = __float2half_rn(r1);
            __half q2 = __float2half_rn(r2), q3 = __float2half_rn(r3);
            *reinterpret_cast<uint32_t*>(&g_h1[o0]) =
                (uint32_t)__half_as_ushort(q0) | ((uint32_t)__half_as_ushort(q1) << 16);
            *reinterpret_cast<uint32_t*>(&g_h1[o1]) =
                (uint32_t)__half_as_ushort(q2) | ((uint32_t)__half_as_ushort(q3) << 16);
        }
    }
}

// ---------------------------------------------------------------------------
// router: logits = h @ W2 + b2 via HMMA (2-limb, 3 products), then softmax,
// shared/local split, top-2, all outputs. CTA = 128 tokens x 64 experts.
// Same scheduling structure as gemm1.
// ---------------------------------------------------------------------------
#define ROWB 80
#define R_ATILE (128 * ROWB)                 // 10240 per limb
#define R_BTILE (64 * ROWB)                  // 5120 per limb
#define R_STAGE (2 * R_ATILE + 2 * R_BTILE)  // 30720
#define R_NSTAGE 3
#define R_KT (HMID / 32)                     // 128
#define LGS 66
#define SMEM_ROUTER (R_NSTAGE * R_STAGE + 128 * LGS * 4 + 512)   // 126464

__global__ void __launch_bounds__(256)
router_hmma_kernel(const float* __restrict__ b2, float* __restrict__ out) {
    extern __shared__ char smem[];
    const uint32_t sbase = smem_u32(smem);
    float* lg   = reinterpret_cast<float*>(smem + R_NSTAGE * R_STAGE);
    float* sinv = lg + 128 * LGS;

    const int tid = threadIdx.x;
    const int wid = tid >> 5;
    const int lid = tid & 31;
    const int tok0 = blockIdx.x * 128;
    const int wm = (wid >> 1) * 32;
    const int wn = (wid & 1) * 32;

    const int lr  = tid >> 1;
    const int cc  = (tid & 1) * 2;
    const char* gA0 = (const char*)(g_h0 + (size_t)(tok0 + lr) * HMID) + cc * 16;
    const char* gA1 = (const char*)(g_h1 + (size_t)(tok0 + lr) * HMID) + cc * 16;
    const uint32_t sA = (uint32_t)lr * ROWB + cc * 16;
    const int br = tid >> 2;
    const int bc = tid & 3;
    const char* gB0 = (const char*)(g_u0 + (size_t)br * HMID) + bc * 16;
    const char* gB1 = (const char*)(g_u1 + (size_t)br * HMID) + bc * 16;
    const uint32_t sB = (uint32_t)br * ROWB + bc * 16;

    float acc[2][4][4];
#pragma unroll
    for (int i = 0; i < 2; i++)
#pragma unroll
        for (int j = 0; j < 4; j++)
#pragma unroll
            for (int k = 0; k < 4; k++) acc[i][j][k] = 0.f;

    auto load_stage = [&](int s, int kt) {
        const uint32_t sb = sbase + s * R_STAGE;
        const int go = kt * 64;
        CP_ASYNC16(sb + sA,      gA0 + go);
        CP_ASYNC16(sb + sA + 16, gA0 + go + 16);
        CP_ASYNC16(sb + R_ATILE + sA,      gA1 + go);
        CP_ASYNC16(sb + R_ATILE + sA + 16, gA1 + go + 16);
        CP_ASYNC16(sb + 2 * R_ATILE + sB,           gB0 + go);
        CP_ASYNC16(sb + 2 * R_ATILE + R_BTILE + sB, gB1 + go);
        CP_COMMIT();
    };

    const uint32_t aRow = (uint32_t)(wm + (lid & 15)) * ROWB + (lid >> 4) * 16;
    const uint32_t bRow = (uint32_t)(wn + (lid & 7) + ((lid >> 4) & 1) * 8) * ROWB
                        + ((lid >> 3) & 1) * 16;

    load_stage(0, 0);
    load_stage(1, 1);

    for (int kt = 0; kt < R_KT; kt++) {
        if (kt < R_KT - 1) {
            asm volatile("cp.async.wait_group 1;" ::: "memory");
        } else {
            asm volatile("cp.async.wait_group 0;" ::: "memory");
        }
        __syncthreads();

        const uint32_t sb = sbase + (kt % R_NSTAGE) * R_STAGE;
#pragma unroll
        for (int k16 = 0; k16 < 2; k16++) {
            const uint32_t kOff = k16 * 32;
            uint32_t b0[2][4], b1f[2][4];
#pragma unroll
            for (int nt2 = 0; nt2 < 2; nt2++) {
                ldsm_x4(b0[nt2],  sb + 2 * R_ATILE + bRow + kOff + nt2 * 16 * ROWB);
                ldsm_x4(b1f[nt2], sb + 2 * R_ATILE + R_BTILE + bRow + kOff + nt2 * 16 * ROWB);
            }
            uint32_t a0[2][4], a1[2][4];
#pragma unroll
            for (int mt = 0; mt < 2; mt++)
                ldsm_x4(a0[mt], sb + aRow + kOff + mt * 16 * ROWB);
#pragma unroll
            for (int mt = 0; mt < 2; mt++)
                ldsm_x4(a1[mt], sb + R_ATILE + aRow + kOff + mt * 16 * ROWB);

#pragma unroll
            for (int mt = 0; mt < 2; mt++)
#pragma unroll
                for (int nt = 0; nt < 4; nt++) {
                    const int n2 = nt >> 1, h = (nt & 1) * 2;
                    mma16816(acc[mt][nt], a0[mt], b0[n2][h], b0[n2][h + 1]);
                }
            if (k16 == 0 && kt + 2 < R_KT)
                load_stage((kt + 2) % R_NSTAGE, kt + 2);
#pragma unroll
            for (int mt = 0; mt < 2; mt++)
#pragma unroll
                for (int nt = 0; nt < 4; nt++) {
                    const int n2 = nt >> 1, h = (nt & 1) * 2;
                    mma16816(acc[mt][nt], a0[mt], b1f[n2][h], b1f[n2][h + 1]);
                }
#pragma unroll
            for (int mt = 0; mt < 2; mt++)
#pragma unroll
                for (int nt = 0; nt < 4; nt++) {
                    const int n2 = nt >> 1, h = (nt & 1) * 2;
                    mma16816(acc[mt][nt], a1[mt], b0[n2][h], b0[n2][h + 1]);
                }
        }
    }

    // write logits (+bias) into smem
    {
        const int g = lid >> 2;
        const int i2 = (lid & 3) * 2;
#pragma unroll
        for (int nt = 0; nt < 4; nt++) {
            const int col = wn + nt * 8 + i2;
            const float bx = b2[col], by = b2[col + 1];
#pragma unroll
            for (int mt = 0; mt < 2; mt++) {
                const int row = wm + mt * 16 + g;
                *reinterpret_cast<float2*>(&lg[row * LGS + col]) =
                    make_float2(acc[mt][nt][0] + bx, acc[mt][nt][1] + by);
                *reinterpret_cast<float2*>(&lg[(row + 8) * LGS + col]) =
                    make_float2(acc[mt][nt][2] + bx, acc[mt][nt][3] + by);
            }
        }
    }
    __syncthreads();

    // softmax + top-2 + small outputs: one thread per token
    if (tid < 128) {
        const int tok = tok0 + tid;
        float* row = &lg[tid * LGS];
        float mx = -1e30f;
#pragma unroll
        for (int e = 0; e < NEXP; e++) mx = fmaxf(mx, row[e]);
        float s = 0.f;
#pragma unroll
        for (int e = 0; e < NEXP; e++) {
            float ev = expf(row[e] - mx);
            row[e] = ev;
            s += ev;
        }
        float inv = 1.0f / s;
        sinv[tid] = inv;

        float v1 = -1.0f, v2 = -1.0f;
        int i1 = 0, i2v = 0;
#pragma unroll
        for (int e = NSHARED; e < NEXP; e++) {
            float v = row[e];
            if (v > v1)      { v2 = v1; i2v = i1; v1 = v; i1 = e; }
            else if (v > v2) { v2 = v;  i2v = e; }
        }
#pragma unroll
        for (int e = 0; e < NSHARED; e++)
            out[G_OFF + (size_t)tok * NSHARED + e] = row[e] * inv;
        out[LW_OFF + (size_t)tok * TOPK + 0] = v1 * inv;
        out[LW_OFF + (size_t)tok * TOPK + 1] = v2 * inv;
        out[LI_OFF + (size_t)tok * TOPK + 0] = (float)(i1 - NSHARED);
        out[LI_OFF + (size_t)tok * TOPK + 1] = (float)(i2v - NSHARED);
    }
    __syncthreads();

    // full weights matrix: 128 tokens x 32 float2 = 4096 float2, 16 per thread
#pragma unroll
    for (int hh = 0; hh < 16; hh++) {
        int f = tid + 256 * hh;
        int tr = f >> 5;
        int ec = (f & 31) * 2;
        float inv = sinv[tr];
        float2 v = *reinterpret_cast<const float2*>(&lg[tr * LGS + ec]);
        v.x *= inv; v.y *= inv;
        *reinterpret_cast<float2*>(
            &out[W_OFF + (size_t)(tok0 + tr) * NEXP + ec]) = v;
    }
}

// ---------------------------------------------------------------------------
extern "C" void kernel_launch(void* const* d_in, const int* in_sizes, int n_in,
                              void* d_out, int out_size) {
    const float* x  = (const float*)d_in[0];
    const float* W1 = (const float*)d_in[1];
    const float* b1 = (const float*)d_in[2];
    const float* W2 = (const float*)d_in[3];
    const float* b2 = (const float*)d_in[4];
    float* out = (float*)d_out;

    static int attr_done = 0;
    if (!attr_done) {
        cudaFuncSetAttribute(gemm1_hmma_kernel,
                             cudaFuncAttributeMaxDynamicSharedMemorySize, SMEM_GEMM);
        cudaFuncSetAttribute(router_hmma_kernel,
                             cudaFuncAttributeMaxDynamicSharedMemorySize, SMEM_ROUTER);
        attr_done = 1;
    }

    conv_x_kernel<<<(NTOK * DIN) / (256 * 4), 256>>>(x);
    conv_w1_kernel<<<dim3(HMID / 32, DIN / 32), dim3(32, 8)>>>(W1);
    conv_w2_kernel<<<dim3(NEXP / 32, HMID / 32), dim3(32, 8)>>>(W2);
    gemm1_hmma_kernel<<<dim3(HMID / 128, NTOK / 128), 256, SMEM_GEMM>>>(b1);
    router_hmma_kernel<<<NTOK / 128, 256, SMEM_ROUTER>>>(b2, out);
}

// round 9
// speedup vs baseline: 2.6520x; 1.0070x over previous
#include <cuda_runtime.h>
#include <cuda_fp16.h>
#include <math.h>
#include <stdint.h>

// ---------------------------------------------------------------------------
// Problem constants
// ---------------------------------------------------------------------------
#define NTOK  16384
#define DIN   2048
#define HMID  4096
#define NEXP  64
#define NSHARED 8
#define TOPK  2

// Output layout (flattened concat of the reference tuple)
#define G_OFF  0
#define LW_OFF (NTOK * NSHARED)
#define LI_OFF (LW_OFF + NTOK * TOPK)
#define W_OFF  (LI_OFF + NTOK * TOPK)

// ---------------------------------------------------------------------------
// Scratch (static device arrays; no allocation)
// ---------------------------------------------------------------------------
__device__ __half g_x0[(size_t)NTOK * DIN];           // x limb planes
__device__ __half g_x1[(size_t)NTOK * DIN];
__device__ __half g_w0[(size_t)HMID * DIN];           // W1^T limb planes
__device__ __half g_w1[(size_t)HMID * DIN];
__device__ __half g_h0[(size_t)NTOK * HMID];          // h limb planes
__device__ __half g_h1[(size_t)NTOK * HMID];
__device__ __half g_u0[(size_t)NEXP * HMID];          // W2^T limb planes
__device__ __half g_u1[(size_t)NEXP * HMID];

#define KSPLIT 4
#define RK (HMID / KSPLIT)                            // 1024
__device__ float g_part[KSPLIT][NTOK][NEXP];          // 16.8 MB partial logits

__device__ __forceinline__ uint32_t smem_u32(const void* p) {
    uint32_t a;
    asm("{ .reg .u64 t; cvta.to.shared.u64 t, %1; cvt.u32.u64 %0, t; }"
        : "=r"(a) : "l"(p));
    return a;
}

__device__ __forceinline__ float gelu_exact(float v) {
    return 0.5f * v * (1.0f + erff(v * 0.70710678118654752440f));
}

__device__ __forceinline__ void ldsm_x4(uint32_t* r, uint32_t addr) {
    asm volatile("ldmatrix.sync.aligned.m8n8.x4.shared.b16 {%0,%1,%2,%3}, [%4];"
                 : "=r"(r[0]), "=r"(r[1]), "=r"(r[2]), "=r"(r[3]) : "r"(addr));
}

__device__ __forceinline__ void mma16816(float* d, const uint32_t* a,
                                         uint32_t b0, uint32_t b1) {
    asm volatile(
        "mma.sync.aligned.m16n8k16.row.col.f32.f16.f16.f32 "
        "{%0,%1,%2,%3}, {%4,%5,%6,%7}, {%8,%9}, {%0,%1,%2,%3};"
        : "+f"(d[0]), "+f"(d[1]), "+f"(d[2]), "+f"(d[3])
        : "r"(a[0]), "r"(a[1]), "r"(a[2]), "r"(a[3]), "r"(b0), "r"(b1));
}

#define CP_ASYNC16(dst, src) \
    asm volatile("cp.async.cg.shared.global [%0], [%1], 16;" \
                 :: "r"(dst), "l"(src) : "memory")
#define CP_COMMIT() asm volatile("cp.async.commit_group;" ::: "memory")

__device__ __forceinline__ uint32_t pack_limbs(float x, float y,
                                               float& rx, float& ry) {
    __half hx = __float2half_rn(x), hy = __float2half_rn(y);
    rx = x - __half2float(hx);
    ry = y - __half2float(hy);
    return (uint32_t)__half_as_ushort(hx) | ((uint32_t)__half_as_ushort(hy) << 16);
}

// ---------------------------------------------------------------------------
// conv_x: split x into 2 fp16 limb planes (row-major, K contiguous)
// ---------------------------------------------------------------------------
__global__ void __launch_bounds__(256)
conv_x_kernel(const float* __restrict__ x) {
    size_t i = ((size_t)blockIdx.x * 256 + threadIdx.x) * 4;
    float4 v = *reinterpret_cast<const float4*>(&x[i]);
    float a[4] = {v.x, v.y, v.z, v.w};
    unsigned short u0[4], u1[4];
#pragma unroll
    for (int j = 0; j < 4; j++) {
        __half h0 = __float2half_rn(a[j]);
        float r = a[j] - __half2float(h0);
        __half h1 = __float2half_rn(r);
        u0[j] = __half_as_ushort(h0);
        u1[j] = __half_as_ushort(h1);
    }
    *reinterpret_cast<uint2*>(&g_x0[i]) =
        make_uint2((uint32_t)u0[0] | ((uint32_t)u0[1] << 16),
                   (uint32_t)u0[2] | ((uint32_t)u0[3] << 16));
    *reinterpret_cast<uint2*>(&g_x1[i]) =
        make_uint2((uint32_t)u1[0] | ((uint32_t)u1[1] << 16),
                   (uint32_t)u1[2] | ((uint32_t)u1[3] << 16));
}

// ---------------------------------------------------------------------------
// conv_w1: transpose W1 [K,N] -> [N,K], split into 2 fp16 limb planes
// ---------------------------------------------------------------------------
__global__ void __launch_bounds__(256)
conv_w1_kernel(const float* __restrict__ W1) {
    __shared__ float tile[32][33];
    const int tx = threadIdx.x, ty = threadIdx.y;
    const int n0 = blockIdx.x * 32;
    const int k0 = blockIdx.y * 32;
#pragma unroll
    for (int j = 0; j < 4; j++)
        tile[ty + j * 8][tx] = W1[(size_t)(k0 + ty + j * 8) * HMID + n0 + tx];
    __syncthreads();
#pragma unroll
    for (int j = 0; j < 4; j++) {
        float v = tile[tx][ty + j * 8];
        __half h0 = __float2half_rn(v);
        float r = v - __half2float(h0);
        size_t o = (size_t)(n0 + ty + j * 8) * DIN + k0 + tx;
        g_w0[o] = h0;
        g_w1[o] = __float2half_rn(r);
    }
}

// ---------------------------------------------------------------------------
// conv_w2: transpose W2 [K=4096, 64] -> [64][4096], split into 2 limb planes
// ---------------------------------------------------------------------------
__global__ void __launch_bounds__(256)
conv_w2_kernel(const float* __restrict__ W2) {
    __shared__ float tile[32][33];
    const int tx = threadIdx.x, ty = threadIdx.y;
    const int n0 = blockIdx.x * 32;
    const int k0 = blockIdx.y * 32;
#pragma unroll
    for (int j = 0; j < 4; j++)
        tile[ty + j * 8][tx] = W2[(size_t)(k0 + ty + j * 8) * NEXP + n0 + tx];
    __syncthreads();
#pragma unroll
    for (int j = 0; j < 4; j++) {
        float v = tile[tx][ty + j * 8];
        __half h0 = __float2half_rn(v);
        float r = v - __half2float(h0);
        size_t o = (size_t)(n0 + ty + j * 8) * HMID + k0 + tx;
        g_u0[o] = h0;
        g_u1[o] = __float2half_rn(r);
    }
}

// ---------------------------------------------------------------------------
// gemm1: h = gelu(x @ W1 + b1) via mma.sync fp16 2-limb, 3 products.
// (unchanged — known-good 63% tensor configuration)
// ---------------------------------------------------------------------------
#define TILE64  (128 * 64)             // 8192 bytes per limb tile
#define STAGE64 (4 * TILE64)           // 32768
#define GSTAGES 3
#define SMEM_GEMM (GSTAGES * STAGE64)  // 98304
#define KT (DIN / 32)                  // 64

__global__ void __launch_bounds__(256, 2)
gemm1_hmma_kernel(const float* __restrict__ b1) {
    extern __shared__ char smem[];
    const uint32_t sbase = smem_u32(smem);
    const int tid = threadIdx.x;
    const int wid = tid >> 5;
    const int lid = tid & 31;
    const int row0 = blockIdx.y * 128;
    const int col0 = blockIdx.x * 128;
    const int wm = (wid >> 2) * 64;
    const int wn = (wid & 3) * 32;

    const int lr = tid >> 1;
    const int cc = (tid & 1) * 2;
    const int mS = (lr >> 1) & 3;
    const uint32_t dst0 = (uint32_t)lr * 64 + (uint32_t)(((cc)     ^ mS) << 4);
    const uint32_t dst1 = (uint32_t)lr * 64 + (uint32_t)(((cc + 1) ^ mS) << 4);
    const char* gA0 = (const char*)(g_x0 + (size_t)(row0 + lr) * DIN) + cc * 16;
    const char* gA1 = (const char*)(g_x1 + (size_t)(row0 + lr) * DIN) + cc * 16;
    const char* gB0 = (const char*)(g_w0 + (size_t)(col0 + lr) * DIN) + cc * 16;
    const char* gB1 = (const char*)(g_w1 + (size_t)(col0 + lr) * DIN) + cc * 16;

    float acc[4][4][4];
#pragma unroll
    for (int i = 0; i < 4; i++)
#pragma unroll
        for (int j = 0; j < 4; j++)
#pragma unroll
            for (int k = 0; k < 4; k++) acc[i][j][k] = 0.f;

    auto load_stage = [&](int s, int kt) {
        const uint32_t sb = sbase + s * STAGE64;
        const int go = kt * 64;
        CP_ASYNC16(sb + dst0,              gA0 + go);
        CP_ASYNC16(sb + dst1,              gA0 + go + 16);
        CP_ASYNC16(sb + TILE64 + dst0,     gA1 + go);
        CP_ASYNC16(sb + TILE64 + dst1,     gA1 + go + 16);
        CP_ASYNC16(sb + 2 * TILE64 + dst0, gB0 + go);
        CP_ASYNC16(sb + 2 * TILE64 + dst1, gB0 + go + 16);
        CP_ASYNC16(sb + 3 * TILE64 + dst0, gB1 + go);
        CP_ASYNC16(sb + 3 * TILE64 + dst1, gB1 + go + 16);
        CP_COMMIT();
    };

    const uint32_t aRowB = (uint32_t)(wm + (lid & 15)) * 64;
    const int cidxA = lid >> 4;
    const int mA = ((lid & 15) >> 1) & 3;
    const int brow = (lid & 7) + ((lid >> 4) & 1) * 8;
    const uint32_t bRowB = (uint32_t)(wn + brow) * 64;
    const int cidxB = (lid >> 3) & 1;
    const int mB = (brow >> 1) & 3;
    uint32_t aCol[2], bCol[2];
#pragma unroll
    for (int k16 = 0; k16 < 2; k16++) {
        aCol[k16] = (uint32_t)((((k16 << 1) | cidxA) ^ mA) << 4);
        bCol[k16] = (uint32_t)((((k16 << 1) | cidxB) ^ mB) << 4);
    }

    load_stage(0, 0);
    load_stage(1, 1);

    for (int kt = 0; kt < KT; kt++) {
        if (kt < KT - 1) {
            asm volatile("cp.async.wait_group 1;" ::: "memory");
        } else {
            asm volatile("cp.async.wait_group 0;" ::: "memory");
        }
        __syncthreads();

        const uint32_t sb = sbase + (kt % GSTAGES) * STAGE64;
#pragma unroll
        for (int k16 = 0; k16 < 2; k16++) {
            uint32_t b0[2][4], b1f[2][4];
#pragma unroll
            for (int nt2 = 0; nt2 < 2; nt2++) {
                const uint32_t bo = bRowB + nt2 * 1024 + bCol[k16];
                ldsm_x4(b0[nt2],  sb + 2 * TILE64 + bo);
                ldsm_x4(b1f[nt2], sb + 3 * TILE64 + bo);
            }
            uint32_t a0[4][4], a1[4][4];
#pragma unroll
            for (int mt = 0; mt < 4; mt++)
                ldsm_x4(a0[mt], sb + aRowB + mt * 1024 + aCol[k16]);
#pragma unroll
            for (int mt = 0; mt < 4; mt++)
                ldsm_x4(a1[mt], sb + TILE64 + aRowB + mt * 1024 + aCol[k16]);

#pragma unroll
            for (int mt = 0; mt < 4; mt++)
#pragma unroll
                for (int nt = 0; nt < 4; nt++) {
                    const int n2 = nt >> 1, h = (nt & 1) * 2;
                    mma16816(acc[mt][nt], a0[mt], b0[n2][h], b0[n2][h + 1]);
                }
            if (k16 == 0 && kt + 2 < KT)
                load_stage((kt + 2) % GSTAGES, kt + 2);
#pragma unroll
            for (int mt = 0; mt < 4; mt++)
#pragma unroll
                for (int nt = 0; nt < 4; nt++) {
                    const int n2 = nt >> 1, h = (nt & 1) * 2;
                    mma16816(acc[mt][nt], a0[mt], b1f[n2][h], b1f[n2][h + 1]);
                }
#pragma unroll
            for (int mt = 0; mt < 4; mt++)
#pragma unroll
                for (int nt = 0; nt < 4; nt++) {
                    const int n2 = nt >> 1, h = (nt & 1) * 2;
                    mma16816(acc[mt][nt], a1[mt], b0[n2][h], b0[n2][h + 1]);
                }
        }
    }

    // epilogue: bias + gelu + split into fp16 limbs + store
    const int g = lid >> 2;
    const int i2 = (lid & 3) * 2;
#pragma unroll
    for (int nt = 0; nt < 4; nt++) {
        const int col = col0 + wn + nt * 8 + i2;
        const float bx = b1[col], by = b1[col + 1];
#pragma unroll
        for (int mt = 0; mt < 4; mt++) {
            const int row = row0 + wm + mt * 16 + g;
            float lox = gelu_exact(acc[mt][nt][0] + bx);
            float loy = gelu_exact(acc[mt][nt][1] + by);
            float hix = gelu_exact(acc[mt][nt][2] + bx);
            float hiy = gelu_exact(acc[mt][nt][3] + by);
            float r0, r1, r2, r3;
            uint32_t p0 = pack_limbs(lox, loy, r0, r1);
            uint32_t p1 = pack_limbs(hix, hiy, r2, r3);
            size_t o0 = (size_t)row * HMID + col;
            size_t o1 = (size_t)(row + 8) * HMID + col;
            *reinterpret_cast<uint32_t*>(&g_h0[o0]) = p0;
            *reinterpret_cast<uint32_t*>(&g_h0[o1]) = p1;
            __half q0 = __float2half_rn(r0), q1 = __float2half_rn(r1);
            __half q2 = __float2half_rn(r2), q3 = __float2half_rn(r3);
            *reinterpret_cast<uint32_t*>(&g_h1[o0]) =
                (uint32_t)__half_as_ushort(q0) | ((uint32_t)__half_as_ushort(q1) << 16);
            *reinterpret_cast<uint32_t*>(&g_h1[o1]) =
                (uint32_t)__half_as_ushort(q2) | ((uint32_t)__half_as_ushort(q3) << 16);
        }
    }
}

// ---------------------------------------------------------------------------
// router_partial: partial logits over a K-slice of 1024.
// grid (NTOK/128, KSPLIT), 2 CTAs/SM. Stores raw fp32 partials (no bias).
// ---------------------------------------------------------------------------
#define ROWB 80
#define R_ATILE (128 * ROWB)
#define R_BTILE (64 * ROWB)
#define R_STAGE (2 * R_ATILE + 2 * R_BTILE)  // 30720
#define R_NSTAGE 3
#define R_KT (RK / 32)                       // 32
#define SMEM_RPART (R_NSTAGE * R_STAGE)      // 92160

__global__ void __launch_bounds__(256, 2)
router_partial_kernel() {
    extern __shared__ char smem[];
    const uint32_t sbase = smem_u32(smem);

    const int tid = threadIdx.x;
    const int wid = tid >> 5;
    const int lid = tid & 31;
    const int tok0 = blockIdx.x * 128;
    const int ks = blockIdx.y;
    const int wm = (wid >> 1) * 32;
    const int wn = (wid & 1) * 32;

    const int lr  = tid >> 1;
    const int cc  = (tid & 1) * 2;
    const char* gA0 = (const char*)(g_h0 + (size_t)(tok0 + lr) * HMID + (size_t)ks * RK) + cc * 16;
    const char* gA1 = (const char*)(g_h1 + (size_t)(tok0 + lr) * HMID + (size_t)ks * RK) + cc * 16;
    const uint32_t sA = (uint32_t)lr * ROWB + cc * 16;
    const int br = tid >> 2;
    const int bc = tid & 3;
    const char* gB0 = (const char*)(g_u0 + (size_t)br * HMID + (size_t)ks * RK) + bc * 16;
    const char* gB1 = (const char*)(g_u1 + (size_t)br * HMID + (size_t)ks * RK) + bc * 16;
    const uint32_t sB = (uint32_t)br * ROWB + bc * 16;

    float acc[2][4][4];
#pragma unroll
    for (int i = 0; i < 2; i++)
#pragma unroll
        for (int j = 0; j < 4; j++)
#pragma unroll
            for (int k = 0; k < 4; k++) acc[i][j][k] = 0.f;

    auto load_stage = [&](int s, int kt) {
        const uint32_t sb = sbase + s * R_STAGE;
        const int go = kt * 64;
        CP_ASYNC16(sb + sA,      gA0 + go);
        CP_ASYNC16(sb + sA + 16, gA0 + go + 16);
        CP_ASYNC16(sb + R_ATILE + sA,      gA1 + go);
        CP_ASYNC16(sb + R_ATILE + sA + 16, gA1 + go + 16);
        CP_ASYNC16(sb + 2 * R_ATILE + sB,           gB0 + go);
        CP_ASYNC16(sb + 2 * R_ATILE + R_BTILE + sB, gB1 + go);
        CP_COMMIT();
    };

    const uint32_t aRow = (uint32_t)(wm + (lid & 15)) * ROWB + (lid >> 4) * 16;
    const uint32_t bRow = (uint32_t)(wn + (lid & 7) + ((lid >> 4) & 1) * 8) * ROWB
                        + ((lid >> 3) & 1) * 16;

    load_stage(0, 0);
    load_stage(1, 1);

    for (int kt = 0; kt < R_KT; kt++) {
        if (kt < R_KT - 1) {
            asm volatile("cp.async.wait_group 1;" ::: "memory");
        } else {
            asm volatile("cp.async.wait_group 0;" ::: "memory");
        }
        __syncthreads();

        const uint32_t sb = sbase + (kt % R_NSTAGE) * R_STAGE;
#pragma unroll
        for (int k16 = 0; k16 < 2; k16++) {
            const uint32_t kOff = k16 * 32;
            uint32_t b0[2][4], b1f[2][4];
#pragma unroll
            for (int nt2 = 0; nt2 < 2; nt2++) {
                ldsm_x4(b0[nt2],  sb + 2 * R_ATILE + bRow + kOff + nt2 * 16 * ROWB);
                ldsm_x4(b1f[nt2], sb + 2 * R_ATILE + R_BTILE + bRow + kOff + nt2 * 16 * ROWB);
            }
            uint32_t a0[2][4], a1[2][4];
#pragma unroll
            for (int mt = 0; mt < 2; mt++)
                ldsm_x4(a0[mt], sb + aRow + kOff + mt * 16 * ROWB);
#pragma unroll
            for (int mt = 0; mt < 2; mt++)
                ldsm_x4(a1[mt], sb + R_ATILE + aRow + kOff + mt * 16 * ROWB);

#pragma unroll
            for (int mt = 0; mt < 2; mt++)
#pragma unroll
                for (int nt = 0; nt < 4; nt++) {
                    const int n2 = nt >> 1, h = (nt & 1) * 2;
                    mma16816(acc[mt][nt], a0[mt], b0[n2][h], b0[n2][h + 1]);
                }
            if (k16 == 0 && kt + 2 < R_KT)
                load_stage((kt + 2) % R_NSTAGE, kt + 2);
#pragma unroll
            for (int mt = 0; mt < 2; mt++)
#pragma unroll
                for (int nt = 0; nt < 4; nt++) {
                    const int n2 = nt >> 1, h = (nt & 1) * 2;
                    mma16816(acc[mt][nt], a0[mt], b1f[n2][h], b1f[n2][h + 1]);
                }
#pragma unroll
            for (int mt = 0; mt < 2; mt++)
#pragma unroll
                for (int nt = 0; nt < 4; nt++) {
                    const int n2 = nt >> 1, h = (nt & 1) * 2;
                    mma16816(acc[mt][nt], a1[mt], b0[n2][h], b0[n2][h + 1]);
                }
        }
    }

    // store raw partials (float2, 8B-aligned: col even)
    const int g = lid >> 2;
    const int i2 = (lid & 3) * 2;
#pragma unroll
    for (int nt = 0; nt < 4; nt++) {
        const int col = wn + nt * 8 + i2;
#pragma unroll
        for (int mt = 0; mt < 2; mt++) {
            const int row = wm + mt * 16 + g;
            *reinterpret_cast<float2*>(&g_part[ks][tok0 + row][col]) =
                make_float2(acc[mt][nt][0], acc[mt][nt][1]);
            *reinterpret_cast<float2*>(&g_part[ks][tok0 + row + 8][col]) =
                make_float2(acc[mt][nt][2], acc[mt][nt][3]);
        }
    }
}

// ---------------------------------------------------------------------------
// router_finalize: sum KSPLIT partials + b2, softmax, split, top-2, outputs.
// 128 tokens per CTA, 256 threads. LGS=68: stride divisible by 4 floats so
// float4 smem accesses stay 16B-aligned (LGS=66 caused misaligned ST.128).
// ---------------------------------------------------------------------------
#define LGS 68
#define SMEM_RFIN (128 * LGS * 4 + 512)

__global__ void __launch_bounds__(256)
router_finalize_kernel(const float* __restrict__ b2, float* __restrict__ out) {
    extern __shared__ float rs[];
    float* lg   = rs;
    float* sinv = rs + 128 * LGS;

    const int tid = threadIdx.x;
    const int tok0 = blockIdx.x * 128;

    // sum partials + bias: 128 tokens x 16 float4 groups = 2048, 8 per thread
#pragma unroll
    for (int hh = 0; hh < 8; hh++) {
        int f = tid + 256 * hh;
        int row = f >> 4;
        int c4 = (f & 15) * 4;
        float4 s = *reinterpret_cast<const float4*>(&g_part[0][tok0 + row][c4]);
#pragma unroll
        for (int ks = 1; ks < KSPLIT; ks++) {
            float4 p = *reinterpret_cast<const float4*>(&g_part[ks][tok0 + row][c4]);
            s.x += p.x; s.y += p.y; s.z += p.z; s.w += p.w;
        }
        float4 bb = *reinterpret_cast<const float4*>(&b2[c4]);
        s.x += bb.x; s.y += bb.y; s.z += bb.z; s.w += bb.w;
        *reinterpret_cast<float4*>(&lg[row * LGS + c4]) = s;
    }
    __syncthreads();

    // softmax + top-2 + small outputs: one thread per token
    if (tid < 128) {
        const int tok = tok0 + tid;
        float* row = &lg[tid * LGS];
        float mx = -1e30f;
#pragma unroll
        for (int e = 0; e < NEXP; e++) mx = fmaxf(mx, row[e]);
        float s = 0.f;
#pragma unroll
        for (int e = 0; e < NEXP; e++) {
            float ev = expf(row[e] - mx);
            row[e] = ev;
            s += ev;
        }
        float inv = 1.0f / s;
        sinv[tid] = inv;

        float v1 = -1.0f, v2 = -1.0f;
        int i1 = 0, i2v = 0;
#pragma unroll
        for (int e = NSHARED; e < NEXP; e++) {
            float v = row[e];
            if (v > v1)      { v2 = v1; i2v = i1; v1 = v; i1 = e; }
            else if (v > v2) { v2 = v;  i2v = e; }
        }
#pragma unroll
        for (int e = 0; e < NSHARED; e++)
            out[G_OFF + (size_t)tok * NSHARED + e] = row[e] * inv;
        out[LW_OFF + (size_t)tok * TOPK + 0] = v1 * inv;
        out[LW_OFF + (size_t)tok * TOPK + 1] = v2 * inv;
        out[LI_OFF + (size_t)tok * TOPK + 0] = (float)(i1 - NSHARED);
        out[LI_OFF + (size_t)tok * TOPK + 1] = (float)(i2v - NSHARED);
    }
    __syncthreads();

    // full weights matrix: 128 tokens x 32 float2 = 4096 float2, 16 per thread
#pragma unroll
    for (int hh = 0; hh < 16; hh++) {
        int f = tid + 256 * hh;
        int tr = f >> 5;
        int ec = (f & 31) * 2;
        float inv = sinv[tr];
        float2 v = *reinterpret_cast<const float2*>(&lg[tr * LGS + ec]);
        v.x *= inv; v.y *= inv;
        *reinterpret_cast<float2*>(
            &out[W_OFF + (size_t)(tok0 + tr) * NEXP + ec]) = v;
    }
}

// ---------------------------------------------------------------------------
extern "C" void kernel_launch(void* const* d_in, const int* in_sizes, int n_in,
                              void* d_out, int out_size) {
    const float* x  = (const float*)d_in[0];
    const float* W1 = (const float*)d_in[1];
    const float* b1 = (const float*)d_in[2];
    const float* W2 = (const float*)d_in[3];
    const float* b2 = (const float*)d_in[4];
    float* out = (float*)d_out;

    static int attr_done = 0;
    if (!attr_done) {
        cudaFuncSetAttribute(gemm1_hmma_kernel,
                             cudaFuncAttributeMaxDynamicSharedMemorySize, SMEM_GEMM);
        cudaFuncSetAttribute(router_partial_kernel,
                             cudaFuncAttributeMaxDynamicSharedMemorySize, SMEM_RPART);
        cudaFuncSetAttribute(router_finalize_kernel,
                             cudaFuncAttributeMaxDynamicSharedMemorySize, SMEM_RFIN);
        attr_done = 1;
    }

    conv_x_kernel<<<(NTOK * DIN) / (256 * 4), 256>>>(x);
    conv_w1_kernel<<<dim3(HMID / 32, DIN / 32), dim3(32, 8)>>>(W1);
    conv_w2_kernel<<<dim3(NEXP / 32, HMID / 32), dim3(32, 8)>>>(W2);
    gemm1_hmma_kernel<<<dim3(HMID / 128, NTOK / 128), 256, SMEM_GEMM>>>(b1);
    router_partial_kernel<<<dim3(NTOK / 128, KSPLIT), 256, SMEM_RPART>>>();
    router_finalize_kernel<<<NTOK / 128, 256, SMEM_RFIN>>>(b2, out);
}

// round 11
// speedup vs baseline: 2.6553x; 1.0012x over previous
#include <cuda_runtime.h>
#include <cuda_fp16.h>
#include <math.h>
#include <stdint.h>

// ---------------------------------------------------------------------------
// Problem constants
// ---------------------------------------------------------------------------
#define NTOK  16384
#define DIN   2048
#define HMID  4096
#define NEXP  64
#define NSHARED 8
#define TOPK  2

// Output layout (flattened concat of the reference tuple)
#define G_OFF  0
#define LW_OFF (NTOK * NSHARED)
#define LI_OFF (LW_OFF + NTOK * TOPK)
#define W_OFF  (LI_OFF + NTOK * TOPK)

// ---------------------------------------------------------------------------
// Scratch (static device arrays; no allocation)
// ---------------------------------------------------------------------------
__device__ __half g_x0[(size_t)NTOK * DIN];           // x limb planes
__device__ __half g_x1[(size_t)NTOK * DIN];
__device__ __half g_w0[(size_t)HMID * DIN];           // W1^T limb planes
__device__ __half g_w1[(size_t)HMID * DIN];
__device__ __half g_h0[(size_t)NTOK * HMID];          // h limb planes
__device__ __half g_h1[(size_t)NTOK * HMID];
__device__ __half g_u0[(size_t)NEXP * HMID];          // W2^T limb planes
__device__ __half g_u1[(size_t)NEXP * HMID];

#define KSPLIT 4
#define RK (HMID / KSPLIT)                            // 1024
__device__ float g_part[KSPLIT][NTOK][NEXP];          // 16.8 MB partial logits

__device__ __forceinline__ uint32_t smem_u32(const void* p) {
    uint32_t a;
    asm("{ .reg .u64 t; cvta.to.shared.u64 t, %1; cvt.u32.u64 %0, t; }"
        : "=r"(a) : "l"(p));
    return a;
}

__device__ __forceinline__ float gelu_exact(float v) {
    return 0.5f * v * (1.0f + erff(v * 0.70710678118654752440f));
}

__device__ __forceinline__ void ldsm_x4(uint32_t* r, uint32_t addr) {
    asm volatile("ldmatrix.sync.aligned.m8n8.x4.shared.b16 {%0,%1,%2,%3}, [%4];"
                 : "=r"(r[0]), "=r"(r[1]), "=r"(r[2]), "=r"(r[3]) : "r"(addr));
}

__device__ __forceinline__ void mma16816(float* d, const uint32_t* a,
                                         uint32_t b0, uint32_t b1) {
    asm volatile(
        "mma.sync.aligned.m16n8k16.row.col.f32.f16.f16.f32 "
        "{%0,%1,%2,%3}, {%4,%5,%6,%7}, {%8,%9}, {%0,%1,%2,%3};"
        : "+f"(d[0]), "+f"(d[1]), "+f"(d[2]), "+f"(d[3])
        : "r"(a[0]), "r"(a[1]), "r"(a[2]), "r"(a[3]), "r"(b0), "r"(b1));
}

#define CP_ASYNC16(dst, src) \
    asm volatile("cp.async.cg.shared.global [%0], [%1], 16;" \
                 :: "r"(dst), "l"(src) : "memory")
#define CP_COMMIT() asm volatile("cp.async.commit_group;" ::: "memory")
#define BAR_SYNC(id, cnt) \
    asm volatile("bar.sync %0, %1;" :: "r"(id), "r"(cnt) : "memory")
#define BAR_ARRIVE(id, cnt) \
    asm volatile("bar.arrive %0, %1;" :: "r"(id), "r"(cnt) : "memory")

__device__ __forceinline__ uint32_t pack_limbs(float x, float y,
                                               float& rx, float& ry) {
    __half hx = __float2half_rn(x), hy = __float2half_rn(y);
    rx = x - __half2float(hx);
    ry = y - __half2float(hy);
    return (uint32_t)__half_as_ushort(hx) | ((uint32_t)__half_as_ushort(hy) << 16);
}

// ---------------------------------------------------------------------------
// conv_x: split x into 2 fp16 limb planes (row-major, K contiguous)
// ---------------------------------------------------------------------------
__global__ void __launch_bounds__(256)
conv_x_kernel(const float* __restrict__ x) {
    size_t i = ((size_t)blockIdx.x * 256 + threadIdx.x) * 4;
    float4 v = *reinterpret_cast<const float4*>(&x[i]);
    float a[4] = {v.x, v.y, v.z, v.w};
    unsigned short u0[4], u1[4];
#pragma unroll
    for (int j = 0; j < 4; j++) {
        __half h0 = __float2half_rn(a[j]);
        float r = a[j] - __half2float(h0);
        __half h1 = __float2half_rn(r);
        u0[j] = __half_as_ushort(h0);
        u1[j] = __half_as_ushort(h1);
    }
    *reinterpret_cast<uint2*>(&g_x0[i]) =
        make_uint2((uint32_t)u0[0] | ((uint32_t)u0[1] << 16),
                   (uint32_t)u0[2] | ((uint32_t)u0[3] << 16));
    *reinterpret_cast<uint2*>(&g_x1[i]) =
        make_uint2((uint32_t)u1[0] | ((uint32_t)u1[1] << 16),
                   (uint32_t)u1[2] | ((uint32_t)u1[3] << 16));
}

// ---------------------------------------------------------------------------
// conv_w1: transpose W1 [K,N] -> [N,K], split into 2 fp16 limb planes
// ---------------------------------------------------------------------------
__global__ void __launch_bounds__(256)
conv_w1_kernel(const float* __restrict__ W1) {
    __shared__ float tile[32][33];
    const int tx = threadIdx.x, ty = threadIdx.y;
    const int n0 = blockIdx.x * 32;
    const int k0 = blockIdx.y * 32;
#pragma unroll
    for (int j = 0; j < 4; j++)
        tile[ty + j * 8][tx] = W1[(size_t)(k0 + ty + j * 8) * HMID + n0 + tx];
    __syncthreads();
#pragma unroll
    for (int j = 0; j < 4; j++) {
        float v = tile[tx][ty + j * 8];
        __half h0 = __float2half_rn(v);
        float r = v - __half2float(h0);
        size_t o = (size_t)(n0 + ty + j * 8) * DIN + k0 + tx;
        g_w0[o] = h0;
        g_w1[o] = __float2half_rn(r);
    }
}

// ---------------------------------------------------------------------------
// conv_w2: transpose W2 [K=4096, 64] -> [64][4096], split into 2 limb planes
// ---------------------------------------------------------------------------
__global__ void __launch_bounds__(256)
conv_w2_kernel(const float* __restrict__ W2) {
    __shared__ float tile[32][33];
    const int tx = threadIdx.x, ty = threadIdx.y;
    const int n0 = blockIdx.x * 32;
    const int k0 = blockIdx.y * 32;
#pragma unroll
    for (int j = 0; j < 4; j++)
        tile[ty + j * 8][tx] = W2[(size_t)(k0 + ty + j * 8) * NEXP + n0 + tx];
    __syncthreads();
#pragma unroll
    for (int j = 0; j < 4; j++) {
        float v = tile[tx][ty + j * 8];
        __half h0 = __float2half_rn(v);
        float r = v - __half2float(h0);
        size_t o = (size_t)(n0 + ty + j * 8) * HMID + k0 + tx;
        g_u0[o] = h0;
        g_u1[o] = __float2half_rn(r);
    }
}

// ---------------------------------------------------------------------------
// gemm1: h = gelu(x @ W1 + b1) via mma.sync fp16 2-limb, 3 products.
// Split named-barrier pipeline (corrected):
//   ready[s] (ids 1..3): prologue posts ready[0] ONLY; at round kt the warps
//     post ready[(kt+1)%3] mid-MMA after wait_group confirms stage kt+1.
//     Consumers SYNC at round top — one full round of slack. Each phase:
//     exactly 256 arrivals + 256 syncs. (R10 double-posted ready[1] in the
//     prologue -> premature release -> deadlock.)
//   free[s] (ids 4..6): readers ARRIVE after stage-kt LDSMs; writers SYNC one
//     round later before overwriting.
// ---------------------------------------------------------------------------
#define TILE64  (128 * 64)             // 8192 bytes per limb tile
#define STAGE64 (4 * TILE64)           // 32768
#define GSTAGES 3
#define SMEM_GEMM (GSTAGES * STAGE64)  // 98304
#define KT (DIN / 32)                  // 64

__global__ void __launch_bounds__(256, 2)
gemm1_hmma_kernel(const float* __restrict__ b1) {
    extern __shared__ char smem[];
    const uint32_t sbase = smem_u32(smem);
    const int tid = threadIdx.x;
    const int wid = tid >> 5;
    const int lid = tid & 31;
    const int row0 = blockIdx.y * 128;
    const int col0 = blockIdx.x * 128;
    const int wm = (wid >> 2) * 64;
    const int wn = (wid & 3) * 32;

    // ---- loader mapping: row lr = tid>>1, chunks cc..cc+1 of 4 (16B each) ----
    const int lr = tid >> 1;
    const int cc = (tid & 1) * 2;
    const int mS = (lr >> 1) & 3;
    const uint32_t dst0 = (uint32_t)lr * 64 + (uint32_t)(((cc)     ^ mS) << 4);
    const uint32_t dst1 = (uint32_t)lr * 64 + (uint32_t)(((cc + 1) ^ mS) << 4);
    const char* gA0 = (const char*)(g_x0 + (size_t)(row0 + lr) * DIN) + cc * 16;
    const char* gA1 = (const char*)(g_x1 + (size_t)(row0 + lr) * DIN) + cc * 16;
    const char* gB0 = (const char*)(g_w0 + (size_t)(col0 + lr) * DIN) + cc * 16;
    const char* gB1 = (const char*)(g_w1 + (size_t)(col0 + lr) * DIN) + cc * 16;

    float acc[4][4][4];
#pragma unroll
    for (int i = 0; i < 4; i++)
#pragma unroll
        for (int j = 0; j < 4; j++)
#pragma unroll
            for (int k = 0; k < 4; k++) acc[i][j][k] = 0.f;

    auto load_stage = [&](int s, int kt) {
        const uint32_t sb = sbase + s * STAGE64;
        const int go = kt * 64;
        CP_ASYNC16(sb + dst0,              gA0 + go);
        CP_ASYNC16(sb + dst1,              gA0 + go + 16);
        CP_ASYNC16(sb + TILE64 + dst0,     gA1 + go);
        CP_ASYNC16(sb + TILE64 + dst1,     gA1 + go + 16);
        CP_ASYNC16(sb + 2 * TILE64 + dst0, gB0 + go);
        CP_ASYNC16(sb + 2 * TILE64 + dst1, gB0 + go + 16);
        CP_ASYNC16(sb + 3 * TILE64 + dst0, gB1 + go);
        CP_ASYNC16(sb + 3 * TILE64 + dst1, gB1 + go + 16);
        CP_COMMIT();
    };

    // ---- ldmatrix address components (swizzle masks are mt/nt invariant) ----
    const uint32_t aRowB = (uint32_t)(wm + (lid & 15)) * 64;
    const int cidxA = lid >> 4;
    const int mA = ((lid & 15) >> 1) & 3;
    const int brow = (lid & 7) + ((lid >> 4) & 1) * 8;
    const uint32_t bRowB = (uint32_t)(wn + brow) * 64;
    const int cidxB = (lid >> 3) & 1;
    const int mB = (brow >> 1) & 3;
    uint32_t aCol[2], bCol[2];
#pragma unroll
    for (int k16 = 0; k16 < 2; k16++) {
        aCol[k16] = (uint32_t)((((k16 << 1) | cidxA) ^ mA) << 4);
        bCol[k16] = (uint32_t)((((k16 << 1) | cidxB) ^ mB) << 4);
    }

    // ---- prologue: stages 0,1 in flight; post ready[0] ONLY ----
    load_stage(0, 0);
    load_stage(1, 1);
    asm volatile("cp.async.wait_group 1;" ::: "memory");
    BAR_ARRIVE(1 + 0, 512);                  // ready[0] (stage 1's ready is
                                             // posted by round 0's mid-loop)

    int r0 = 0, r1 = 1, r2 = 2;              // kt%3, (kt+1)%3, (kt+2)%3

    for (int kt = 0; kt < KT; kt++) {
        BAR_SYNC(1 + r0, 512);               // stage kt visible

        const uint32_t sb = sbase + r0 * STAGE64;

        // ================= k16 = 0 =================
        {
            uint32_t b0[2][4], b1f[2][4];
#pragma unroll
            for (int nt2 = 0; nt2 < 2; nt2++) {
                const uint32_t bo = bRowB + nt2 * 1024 + bCol[0];
                ldsm_x4(b0[nt2],  sb + 2 * TILE64 + bo);
                ldsm_x4(b1f[nt2], sb + 3 * TILE64 + bo);
            }
            uint32_t a0[4][4], a1[4][4];
#pragma unroll
            for (int mt = 0; mt < 4; mt++)
                ldsm_x4(a0[mt], sb + aRowB + mt * 1024 + aCol[0]);
#pragma unroll
            for (int mt = 0; mt < 4; mt++)
                ldsm_x4(a1[mt], sb + TILE64 + aRowB + mt * 1024 + aCol[0]);

#pragma unroll
            for (int mt = 0; mt < 4; mt++)
#pragma unroll
                for (int nt = 0; nt < 4; nt++) {
                    const int n2 = nt >> 1, h = (nt & 1) * 2;
                    mma16816(acc[mt][nt], a0[mt], b0[n2][h], b0[n2][h + 1]);
                }
#pragma unroll
            for (int mt = 0; mt < 4; mt++)
#pragma unroll
                for (int nt = 0; nt < 4; nt++) {
                    const int n2 = nt >> 1, h = (nt & 1) * 2;
                    mma16816(acc[mt][nt], a0[mt], b1f[n2][h], b1f[n2][h + 1]);
                }
#pragma unroll
            for (int mt = 0; mt < 4; mt++)
#pragma unroll
                for (int nt = 0; nt < 4; nt++) {
                    const int n2 = nt >> 1, h = (nt & 1) * 2;
                    mma16816(acc[mt][nt], a1[mt], b0[n2][h], b0[n2][h + 1]);
                }
        }

        // ================= k16 = 1 =================
        {
            uint32_t b0[2][4], b1f[2][4];
#pragma unroll
            for (int nt2 = 0; nt2 < 2; nt2++) {
                const uint32_t bo = bRowB + nt2 * 1024 + bCol[1];
                ldsm_x4(b0[nt2],  sb + 2 * TILE64 + bo);
                ldsm_x4(b1f[nt2], sb + 3 * TILE64 + bo);
            }
            uint32_t a0[4][4], a1[4][4];
#pragma unroll
            for (int mt = 0; mt < 4; mt++)
                ldsm_x4(a0[mt], sb + aRowB + mt * 1024 + aCol[1]);
#pragma unroll
            for (int mt = 0; mt < 4; mt++)
                ldsm_x4(a1[mt], sb + TILE64 + aRowB + mt * 1024 + aCol[1]);

            // all stage-kt reads issued -> release it for rewriting (@kt+1)
            if (kt + 3 < KT) BAR_ARRIVE(4 + r0, 512);      // free[kt%3]
            // wait until stage (kt+2)%3's readers (round kt-1) are done
            if (kt >= 1 && kt + 2 < KT) BAR_SYNC(4 + r2, 512);
            if (kt + 2 < KT) load_stage(r2, kt + 2);

#pragma unroll
            for (int mt = 0; mt < 4; mt++)
#pragma unroll
                for (int nt = 0; nt < 4; nt++) {
                    const int n2 = nt >> 1, h = (nt & 1) * 2;
                    mma16816(acc[mt][nt], a0[mt], b0[n2][h], b0[n2][h + 1]);
                }

            // mid-MMA: confirm own copies for stage kt+1, post its ready
            if (kt + 1 < KT) {
                if (kt + 2 < KT) {
                    asm volatile("cp.async.wait_group 1;" ::: "memory");
                } else {
                    asm volatile("cp.async.wait_group 0;" ::: "memory");
                }
                BAR_ARRIVE(1 + r1, 512);                   // ready[(kt+1)%3]
            }

#pragma unroll
            for (int mt = 0; mt < 4; mt++)
#pragma unroll
                for (int nt = 0; nt < 4; nt++) {
                    const int n2 = nt >> 1, h = (nt & 1) * 2;
                    mma16816(acc[mt][nt], a0[mt], b1f[n2][h], b1f[n2][h + 1]);
                }
#pragma unroll
            for (int mt = 0; mt < 4; mt++)
#pragma unroll
                for (int nt = 0; nt < 4; nt++) {
                    const int n2 = nt >> 1, h = (nt & 1) * 2;
                    mma16816(acc[mt][nt], a1[mt], b0[n2][h], b0[n2][h + 1]);
                }
        }

        const int t = r0; r0 = r1; r1 = r2; r2 = t;
    }

    // epilogue: bias + gelu + split into fp16 limbs + store
    const int g = lid >> 2;
    const int i2 = (lid & 3) * 2;
#pragma unroll
    for (int nt = 0; nt < 4; nt++) {
        const int col = col0 + wn + nt * 8 + i2;
        const float bx = b1[col], by = b1[col + 1];
#pragma unroll
        for (int mt = 0; mt < 4; mt++) {
            const int row = row0 + wm + mt * 16 + g;
            float lox = gelu_exact(acc[mt][nt][0] + bx);
            float loy = gelu_exact(acc[mt][nt][1] + by);
            float hix = gelu_exact(acc[mt][nt][2] + bx);
            float hiy = gelu_exact(acc[mt][nt][3] + by);
            float r0f, r1f, r2f, r3f;
            uint32_t p0 = pack_limbs(lox, loy, r0f, r1f);
            uint32_t p1 = pack_limbs(hix, hiy, r2f, r3f);
            size_t o0 = (size_t)row * HMID + col;
            size_t o1 = (size_t)(row + 8) * HMID + col;
            *reinterpret_cast<uint32_t*>(&g_h0[o0]) = p0;
            *reinterpret_cast<uint32_t*>(&g_h0[o1]) = p1;
            __half q0 = __float2half_rn(r0f), q1 = __float2half_rn(r1f);
            __half q2 = __float2half_rn(r2f), q3 = __float2half_rn(r3f);
            *reinterpret_cast<uint32_t*>(&g_h1[o0]) =
                (uint32_t)__half_as_ushort(q0) | ((uint32_t)__half_as_ushort(q1) << 16);
            *reinterpret_cast<uint32_t*>(&g_h1[o1]) =
                (uint32_t)__half_as_ushort(q2) | ((uint32_t)__half_as_ushort(q3) << 16);
        }
    }
}

// ---------------------------------------------------------------------------
// router_partial: partial logits over a K-slice of 1024.
// grid (NTOK/128, KSPLIT), 2 CTAs/SM. Stores raw fp32 partials (no bias).
// ---------------------------------------------------------------------------
#define ROWB 80
#define R_ATILE (128 * ROWB)
#define R_BTILE (64 * ROWB)
#define R_STAGE (2 * R_ATILE + 2 * R_BTILE)  // 30720
#define R_NSTAGE 3
#define R_KT (RK / 32)                       // 32
#define SMEM_RPART (R_NSTAGE * R_STAGE)      // 92160

__global__ void __launch_bounds__(256, 2)
router_partial_kernel() {
    extern __shared__ char smem[];
    const uint32_t sbase = smem_u32(smem);

    const int tid = threadIdx.x;
    const int wid = tid >> 5;
    const int lid = tid & 31;
    const int tok0 = blockIdx.x * 128;
    const int ks = blockIdx.y;
    const int wm = (wid >> 1) * 32;
    const int wn = (wid & 1) * 32;

    const int lr  = tid >> 1;
    const int cc  = (tid & 1) * 2;
    const char* gA0 = (const char*)(g_h0 + (size_t)(tok0 + lr) * HMID + (size_t)ks * RK) + cc * 16;
    const char* gA1 = (const char*)(g_h1 + (size_t)(tok0 + lr) * HMID + (size_t)ks * RK) + cc * 16;
    const uint32_t sA = (uint32_t)lr * ROWB + cc * 16;
    const int br = tid >> 2;
    const int bc = tid & 3;
    const char* gB0 = (const char*)(g_u0 + (size_t)br * HMID + (size_t)ks * RK) + bc * 16;
    const char* gB1 = (const char*)(g_u1 + (size_t)br * HMID + (size_t)ks * RK) + bc * 16;
    const uint32_t sB = (uint32_t)br * ROWB + bc * 16;

    float acc[2][4][4];
#pragma unroll
    for (int i = 0; i < 2; i++)
#pragma unroll
        for (int j = 0; j < 4; j++)
#pragma unroll
            for (int k = 0; k < 4; k++) acc[i][j][k] = 0.f;

    auto load_stage = [&](int s, int kt) {
        const uint32_t sb = sbase + s * R_STAGE;
        const int go = kt * 64;
        CP_ASYNC16(sb + sA,      gA0 + go);
        CP_ASYNC16(sb + sA + 16, gA0 + go + 16);
        CP_ASYNC16(sb + R_ATILE + sA,      gA1 + go);
        CP_ASYNC16(sb + R_ATILE + sA + 16, gA1 + go + 16);
        CP_ASYNC16(sb + 2 * R_ATILE + sB,           gB0 + go);
        CP_ASYNC16(sb + 2 * R_ATILE + R_BTILE + sB, gB1 + go);
        CP_COMMIT();
    };

    const uint32_t aRow = (uint32_t)(wm + (lid & 15)) * ROWB + (lid >> 4) * 16;
    const uint32_t bRow = (uint32_t)(wn + (lid & 7) + ((lid >> 4) & 1) * 8) * ROWB
                        + ((lid >> 3) & 1) * 16;

    load_stage(0, 0);
    load_stage(1, 1);

    for (int kt = 0; kt < R_KT; kt++) {
        if (kt < R_KT - 1) {
            asm volatile("cp.async.wait_group 1;" ::: "memory");
        } else {
            asm volatile("cp.async.wait_group 0;" ::: "memory");
        }
        __syncthreads();

        const uint32_t sb = sbase + (kt % R_NSTAGE) * R_STAGE;
#pragma unroll
        for (int k16 = 0; k16 < 2; k16++) {
            const uint32_t kOff = k16 * 32;
            uint32_t b0[2][4], b1f[2][4];
#pragma unroll
            for (int nt2 = 0; nt2 < 2; nt2++) {
                ldsm_x4(b0[nt2],  sb + 2 * R_ATILE + bRow + kOff + nt2 * 16 * ROWB);
                ldsm_x4(b1f[nt2], sb + 2 * R_ATILE + R_BTILE + bRow + kOff + nt2 * 16 * ROWB);
            }
            uint32_t a0[2][4], a1[2][4];
#pragma unroll
            for (int mt = 0; mt < 2; mt++)
                ldsm_x4(a0[mt], sb + aRow + kOff + mt * 16 * ROWB);
#pragma unroll
            for (int mt = 0; mt < 2; mt++)
                ldsm_x4(a1[mt], sb + R_ATILE + aRow + kOff + mt * 16 * ROWB);

#pragma unroll
            for (int mt = 0; mt < 2; mt++)
#pragma unroll
                for (int nt = 0; nt < 4; nt++) {
                    const int n2 = nt >> 1, h = (nt & 1) * 2;
                    mma16816(acc[mt][nt], a0[mt], b0[n2][h], b0[n2][h + 1]);
                }
            if (k16 == 0 && kt + 2 < R_KT)
                load_stage((kt + 2) % R_NSTAGE, kt + 2);
#pragma unroll
            for (int mt = 0; mt < 2; mt++)
#pragma unroll
                for (int nt = 0; nt < 4; nt++) {
                    const int n2 = nt >> 1, h = (nt & 1) * 2;
                    mma16816(acc[mt][nt], a0[mt], b1f[n2][h], b1f[n2][h + 1]);
                }
#pragma unroll
            for (int mt = 0; mt < 2; mt++)
#pragma unroll
                for (int nt = 0; nt < 4; nt++) {
                    const int n2 = nt >> 1, h = (nt & 1) * 2;
                    mma16816(acc[mt][nt], a1[mt], b0[n2][h], b0[n2][h + 1]);
                }
        }
    }

    // store raw partials (float2, 8B-aligned: col even)
    const int g = lid >> 2;
    const int i2 = (lid & 3) * 2;
#pragma unroll
    for (int nt = 0; nt < 4; nt++) {
        const int col = wn + nt * 8 + i2;
#pragma unroll
        for (int mt = 0; mt < 2; mt++) {
            const int row = wm + mt * 16 + g;
            *reinterpret_cast<float2*>(&g_part[ks][tok0 + row][col]) =
                make_float2(acc[mt][nt][0], acc[mt][nt][1]);
            *reinterpret_cast<float2*>(&g_part[ks][tok0 + row + 8][col]) =
                make_float2(acc[mt][nt][2], acc[mt][nt][3]);
        }
    }
}

// ---------------------------------------------------------------------------
// router_finalize: sum KSPLIT partials + b2, softmax, split, top-2, outputs.
// ---------------------------------------------------------------------------
#define LGS 68
#define SMEM_RFIN (128 * LGS * 4 + 512)

__global__ void __launch_bounds__(256)
router_finalize_kernel(const float* __restrict__ b2, float* __restrict__ out) {
    extern __shared__ float rs[];
    float* lg   = rs;
    float* sinv = rs + 128 * LGS;

    const int tid = threadIdx.x;
    const int tok0 = blockIdx.x * 128;

#pragma unroll
    for (int hh = 0; hh < 8; hh++) {
        int f = tid + 256 * hh;
        int row = f >> 4;
        int c4 = (f & 15) * 4;
        float4 s = *reinterpret_cast<const float4*>(&g_part[0][tok0 + row][c4]);
#pragma unroll
        for (int ks = 1; ks < KSPLIT; ks++) {
            float4 p = *reinterpret_cast<const float4*>(&g_part[ks][tok0 + row][c4]);
            s.x += p.x; s.y += p.y; s.z += p.z; s.w += p.w;
        }
        float4 bb = *reinterpret_cast<const float4*>(&b2[c4]);
        s.x += bb.x; s.y += bb.y; s.z += bb.z; s.w += bb.w;
        *reinterpret_cast<float4*>(&lg[row * LGS + c4]) = s;
    }
    __syncthreads();

    if (tid < 128) {
        const int tok = tok0 + tid;
        float* row = &lg[tid * LGS];
        float mx = -1e30f;
#pragma unroll
        for (int e = 0; e < NEXP; e++) mx = fmaxf(mx, row[e]);
        float s = 0.f;
#pragma unroll
        for (int e = 0; e < NEXP; e++) {
            float ev = expf(row[e] - mx);
            row[e] = ev;
            s += ev;
        }
        float inv = 1.0f / s;
        sinv[tid] = inv;

        float v1 = -1.0f, v2 = -1.0f;
        int i1 = 0, i2v = 0;
#pragma unroll
        for (int e = NSHARED; e < NEXP; e++) {
            float v = row[e];
            if (v > v1)      { v2 = v1; i2v = i1; v1 = v; i1 = e; }
            else if (v > v2) { v2 = v;  i2v = e; }
        }
#pragma unroll
        for (int e = 0; e < NSHARED; e++)
            out[G_OFF + (size_t)tok * NSHARED + e] = row[e] * inv;
        out[LW_OFF + (size_t)tok * TOPK + 0] = v1 * inv;
        out[LW_OFF + (size_t)tok * TOPK + 1] = v2 * inv;
        out[LI_OFF + (size_t)tok * TOPK + 0] = (float)(i1 - NSHARED);
        out[LI_OFF + (size_t)tok * TOPK + 1] = (float)(i2v - NSHARED);
    }
    __syncthreads();

#pragma unroll
    for (int hh = 0; hh < 16; hh++) {
        int f = tid + 256 * hh;
        int tr = f >> 5;
        int ec = (f & 31) * 2;
        float inv = sinv[tr];
        float2 v = *reinterpret_cast<const float2*>(&lg[tr * LGS + ec]);
        v.x *= inv; v.y *= inv;
        *reinterpret_cast<float2*>(
            &out[W_OFF + (size_t)(tok0 + tr) * NEXP + ec]) = v;
    }
}

// ---------------------------------------------------------------------------
extern "C" void kernel_launch(void* const* d_in, const int* in_sizes, int n_in,
                              void* d_out, int out_size) {
    const float* x  = (const float*)d_in[0];
    const float* W1 = (const float*)d_in[1];
    const float* b1 = (const float*)d_in[2];
    const float* W2 = (const float*)d_in[3];
    const float* b2 = (const float*)d_in[4];
    float* out = (float*)d_out;

    static int attr_done = 0;
    if (!attr_done) {
        cudaFuncSetAttribute(gemm1_hmma_kernel,
                             cudaFuncAttributeMaxDynamicSharedMemorySize, SMEM_GEMM);
        cudaFuncSetAttribute(router_partial_kernel,
                             cudaFuncAttributeMaxDynamicSharedMemorySize, SMEM_RPART);
        cudaFuncSetAttribute(router_finalize_kernel,
                             cudaFuncAttributeMaxDynamicSharedMemorySize, SMEM_RFIN);
        attr_done = 1;
    }

    conv_x_kernel<<<(NTOK * DIN) / (256 * 4), 256>>>(x);
    conv_w1_kernel<<<dim3(HMID / 32, DIN / 32), dim3(32, 8)>>>(W1);
    conv_w2_kernel<<<dim3(NEXP / 32, HMID / 32), dim3(32, 8)>>>(W2);
    gemm1_hmma_kernel<<<dim3(HMID / 128, NTOK / 128), 256, SMEM_GEMM>>>(b1);
    router_partial_kernel<<<dim3(NTOK / 128, KSPLIT), 256, SMEM_RPART>>>();
    router_finalize_kernel<<<NTOK / 128, 256, SMEM_RFIN>>>(b2, out);
}